// round 1
// baseline (speedup 1.0000x reference)
#include <cuda_runtime.h>
#include <math.h>

#define EDIM 1024
#define BDIM 4
#define HDIM 16
#define DHD 64
#define LQ 512
#define SK 1024
#define BH 64   // BDIM*HDIM

// ---------------- scratch (static device globals; no allocation) ----------------
__device__ float g_Qh [BH*LQ*DHD];
__device__ float g_K1h[BH*SK*DHD];
__device__ float g_K2h[BH*SK*DHD];
__device__ float g_V1h[BH*SK*DHD];
__device__ float g_V2h[BH*SK*DHD];
__device__ float g_G1h[BH*LQ*DHD];
__device__ float g_G2h[BH*LQ*DHD];
__device__ float g_ll [BH*LQ];
__device__ float g_vv [BH*SK];
__device__ float g_aa [BH*SK];
__device__ float g_va [BH*SK];
__device__ float g_Attn[BH*LQ*SK];          // 134 MB logits->probs scratch
__device__ float g_Comb[LQ*BDIM*EDIM];      // gated combined output pre o-proj

// ---------------- generic projection GEMM: Y = X@W + b  -------------------------
// X: [N, 1024] row-major, W: [1024, 1024] row-major (in,out).
// mode 0: write head-split layout [BH, npos, DH], value scaled
// mode 1: sigmoid(v), head-split layout
// mode 2: plain [N, E] (final output projection)
__global__ void k_gemm(const float* __restrict__ X, const float* __restrict__ W,
                       const float* __restrict__ bias, float* __restrict__ out,
                       int N, int npos, float scale, int mode)
{
    __shared__ float sA[16][64];   // [k][m]
    __shared__ float sB[16][64];   // [k][n]
    const int bm = blockIdx.y << 6;
    const int bn = blockIdx.x << 6;
    const int tid = threadIdx.x;
    const int tx = tid & 15, ty = tid >> 4;
    float acc[4][4] = {};
    for (int k0 = 0; k0 < EDIM; k0 += 16) {
#pragma unroll
        for (int i = 0; i < 4; i++) {
            int e = tid + (i << 8);
            int r = e >> 4, kk = e & 15;
            sA[kk][r] = X[(size_t)(bm + r) * EDIM + k0 + kk];
        }
#pragma unroll
        for (int i = 0; i < 4; i++) {
            int e = tid + (i << 8);
            int kk = e >> 6, c = e & 63;
            sB[kk][c] = W[(size_t)(k0 + kk) * EDIM + bn + c];
        }
        __syncthreads();
#pragma unroll
        for (int kk = 0; kk < 16; kk++) {
            float a0 = sA[kk][ty*4+0], a1 = sA[kk][ty*4+1];
            float a2 = sA[kk][ty*4+2], a3 = sA[kk][ty*4+3];
            float4 bb = *(const float4*)&sB[kk][tx*4];
            acc[0][0] = fmaf(a0, bb.x, acc[0][0]); acc[0][1] = fmaf(a0, bb.y, acc[0][1]);
            acc[0][2] = fmaf(a0, bb.z, acc[0][2]); acc[0][3] = fmaf(a0, bb.w, acc[0][3]);
            acc[1][0] = fmaf(a1, bb.x, acc[1][0]); acc[1][1] = fmaf(a1, bb.y, acc[1][1]);
            acc[1][2] = fmaf(a1, bb.z, acc[1][2]); acc[1][3] = fmaf(a1, bb.w, acc[1][3]);
            acc[2][0] = fmaf(a2, bb.x, acc[2][0]); acc[2][1] = fmaf(a2, bb.y, acc[2][1]);
            acc[2][2] = fmaf(a2, bb.z, acc[2][2]); acc[2][3] = fmaf(a2, bb.w, acc[2][3]);
            acc[3][0] = fmaf(a3, bb.x, acc[3][0]); acc[3][1] = fmaf(a3, bb.y, acc[3][1]);
            acc[3][2] = fmaf(a3, bb.z, acc[3][2]); acc[3][3] = fmaf(a3, bb.w, acc[3][3]);
        }
        __syncthreads();
    }
#pragma unroll
    for (int i = 0; i < 4; i++) {
        int row = bm + ty*4 + i;
#pragma unroll
        for (int j = 0; j < 4; j++) {
            int col = bn + tx*4 + j;
            float v = (acc[i][j] + bias[col]) * scale;
            if (mode == 1) v = 1.f / (1.f + expf(-v));
            if (mode == 2) {
                out[(size_t)row * EDIM + col] = v;
            } else {
                int pos = row >> 2;         // B = 4
                int b   = row & 3;
                int h   = col >> 6, d = col & 63;
                out[((size_t)(b*HDIM + h) * npos + pos) * DHD + d] = v;
            }
        }
    }
}

// ---------------- per-row stats ----------------
__global__ void k_qstats(const float* __restrict__ Q, float* __restrict__ ll)
{
    int gw = (blockIdx.x * blockDim.x + threadIdx.x) >> 5;
    int lane = threadIdx.x & 31;
    if (gw >= BH*LQ) return;
    const float* q = Q + (size_t)gw * DHD;
    float a0 = q[lane], a1 = q[lane + 32];
    float s = a0*a0 + a1*a1;
#pragma unroll
    for (int o = 16; o; o >>= 1) s += __shfl_xor_sync(0xffffffffu, s, o);
    if (!lane) ll[gw] = s;
}

__global__ void k_kstats(const float* __restrict__ K1, const float* __restrict__ K2,
                         float* __restrict__ vv, float* __restrict__ aa, float* __restrict__ va)
{
    int gw = (blockIdx.x * blockDim.x + threadIdx.x) >> 5;
    int lane = threadIdx.x & 31;
    if (gw >= BH*SK) return;
    const float* a = K1 + (size_t)gw * DHD;
    const float* b = K2 + (size_t)gw * DHD;
    float a0 = a[lane], a1 = a[lane + 32];
    float b0 = b[lane], b1 = b[lane + 32];
    float svv = a0*a0 + a1*a1, saa = b0*b0 + b1*b1, sva = a0*b0 + a1*b1;
#pragma unroll
    for (int o = 16; o; o >>= 1) {
        svv += __shfl_xor_sync(0xffffffffu, svv, o);
        saa += __shfl_xor_sync(0xffffffffu, saa, o);
        sva += __shfl_xor_sync(0xffffffffu, sva, o);
    }
    if (!lane) { vv[gw] = svv; aa[gw] = saa; va[gw] = sva; }
}

// ---------------- logits: lv + la - 1.5*sqrt(gram det) -> Attn ----------------
__global__ void k_logits(const float* __restrict__ Qh, const float* __restrict__ K1h,
                         const float* __restrict__ K2h, const float* __restrict__ ll,
                         const float* __restrict__ vv, const float* __restrict__ aa,
                         const float* __restrict__ va, float* __restrict__ A)
{
    __shared__ float sQ [64][64];   // [d][l]
    __shared__ float sK1[64][64];   // [d][s]
    __shared__ float sK2[64][64];
    const int bh = blockIdx.z;
    const int l0 = blockIdx.y << 6;
    const int s0 = blockIdx.x << 6;
    const int tid = threadIdx.x;
    const float* qb  = Qh  + ((size_t)bh * LQ + l0) * DHD;
    const float* k1b = K1h + ((size_t)bh * SK + s0) * DHD;
    const float* k2b = K2h + ((size_t)bh * SK + s0) * DHD;
#pragma unroll
    for (int i = 0; i < 4; i++) {
        int f = tid + (i << 8);
        int r = f & 63;       // row within tile (fastest over lanes -> conflict-free STS)
        int dv = f >> 6;      // float4 index along d
        float4 q4 = *(const float4*)(qb + (size_t)r * DHD + dv*4);
        sQ[dv*4+0][r] = q4.x; sQ[dv*4+1][r] = q4.y; sQ[dv*4+2][r] = q4.z; sQ[dv*4+3][r] = q4.w;
        float4 u4 = *(const float4*)(k1b + (size_t)r * DHD + dv*4);
        sK1[dv*4+0][r] = u4.x; sK1[dv*4+1][r] = u4.y; sK1[dv*4+2][r] = u4.z; sK1[dv*4+3][r] = u4.w;
        float4 w4 = *(const float4*)(k2b + (size_t)r * DHD + dv*4);
        sK2[dv*4+0][r] = w4.x; sK2[dv*4+1][r] = w4.y; sK2[dv*4+2][r] = w4.z; sK2[dv*4+3][r] = w4.w;
    }
    __syncthreads();
    const int tx = tid & 15, ty = tid >> 4;
    float lv[4][4] = {}, la[4][4] = {};
#pragma unroll 8
    for (int d = 0; d < 64; d++) {
        float a0 = sQ[d][ty*4+0], a1 = sQ[d][ty*4+1];
        float a2 = sQ[d][ty*4+2], a3 = sQ[d][ty*4+3];
        float4 b1 = *(const float4*)&sK1[d][tx*4];
        float4 b2 = *(const float4*)&sK2[d][tx*4];
        lv[0][0]=fmaf(a0,b1.x,lv[0][0]); lv[0][1]=fmaf(a0,b1.y,lv[0][1]); lv[0][2]=fmaf(a0,b1.z,lv[0][2]); lv[0][3]=fmaf(a0,b1.w,lv[0][3]);
        lv[1][0]=fmaf(a1,b1.x,lv[1][0]); lv[1][1]=fmaf(a1,b1.y,lv[1][1]); lv[1][2]=fmaf(a1,b1.z,lv[1][2]); lv[1][3]=fmaf(a1,b1.w,lv[1][3]);
        lv[2][0]=fmaf(a2,b1.x,lv[2][0]); lv[2][1]=fmaf(a2,b1.y,lv[2][1]); lv[2][2]=fmaf(a2,b1.z,lv[2][2]); lv[2][3]=fmaf(a2,b1.w,lv[2][3]);
        lv[3][0]=fmaf(a3,b1.x,lv[3][0]); lv[3][1]=fmaf(a3,b1.y,lv[3][1]); lv[3][2]=fmaf(a3,b1.z,lv[3][2]); lv[3][3]=fmaf(a3,b1.w,lv[3][3]);
        la[0][0]=fmaf(a0,b2.x,la[0][0]); la[0][1]=fmaf(a0,b2.y,la[0][1]); la[0][2]=fmaf(a0,b2.z,la[0][2]); la[0][3]=fmaf(a0,b2.w,la[0][3]);
        la[1][0]=fmaf(a1,b2.x,la[1][0]); la[1][1]=fmaf(a1,b2.y,la[1][1]); la[1][2]=fmaf(a1,b2.z,la[1][2]); la[1][3]=fmaf(a1,b2.w,la[1][3]);
        la[2][0]=fmaf(a2,b2.x,la[2][0]); la[2][1]=fmaf(a2,b2.y,la[2][1]); la[2][2]=fmaf(a2,b2.z,la[2][2]); la[2][3]=fmaf(a2,b2.w,la[2][3]);
        la[3][0]=fmaf(a3,b2.x,la[3][0]); la[3][1]=fmaf(a3,b2.y,la[3][1]); la[3][2]=fmaf(a3,b2.z,la[3][2]); la[3][3]=fmaf(a3,b2.w,la[3][3]);
    }
    float llr[4], vvc[4], aac[4], vac[4];
#pragma unroll
    for (int i = 0; i < 4; i++) llr[i] = ll[bh*LQ + l0 + ty*4 + i];
#pragma unroll
    for (int j = 0; j < 4; j++) {
        int c = bh*SK + s0 + tx*4 + j;
        vvc[j] = vv[c]; aac[j] = aa[c]; vac[j] = va[c];
    }
    float* outp = A + (size_t)bh * LQ * SK;
#pragma unroll
    for (int i = 0; i < 4; i++) {
        int row = l0 + ty*4 + i;
        float4 o4;
        float res[4];
#pragma unroll
        for (int j = 0; j < 4; j++) {
            float LV = lv[i][j], LA = la[i][j];
            float det = llr[i] * (vvc[j]*aac[j] - vac[j]*vac[j])
                      - LV * (LV*aac[j] - LA*vac[j])
                      + LA * (LV*vac[j] - LA*vvc[j]);
            det = fmaxf(det, 1e-8f);
            res[j] = LV + LA - 1.5f * sqrtf(det);
        }
        o4.x = res[0]; o4.y = res[1]; o4.z = res[2]; o4.w = res[3];
        *(float4*)(outp + (size_t)row * SK + s0 + tx*4) = o4;
    }
}

// ---------------- softmax over S (in place) ----------------
__global__ void k_softmax(float* __restrict__ A)
{
    const int row = blockIdx.x;
    float* p = A + (size_t)row * SK;
    const int t = threadIdx.x;                 // 256 threads, 4 elems each
    float x0 = p[t], x1 = p[t+256], x2 = p[t+512], x3 = p[t+768];
    float m = fmaxf(fmaxf(x0, x1), fmaxf(x2, x3));
    __shared__ float sred[8];
#pragma unroll
    for (int o = 16; o; o >>= 1) m = fmaxf(m, __shfl_xor_sync(0xffffffffu, m, o));
    if ((t & 31) == 0) sred[t >> 5] = m;
    __syncthreads();
    if (t < 8) {
        float v = sred[t];
#pragma unroll
        for (int o = 4; o; o >>= 1) v = fmaxf(v, __shfl_xor_sync(0xffu, v, o));
        sred[t] = v;
    }
    __syncthreads();
    m = sred[0];
    float e0 = expf(x0 - m), e1 = expf(x1 - m), e2 = expf(x2 - m), e3 = expf(x3 - m);
    float s = e0 + e1 + e2 + e3;
#pragma unroll
    for (int o = 16; o; o >>= 1) s += __shfl_xor_sync(0xffffffffu, s, o);
    __shared__ float sred2[8];
    if ((t & 31) == 0) sred2[t >> 5] = s;
    __syncthreads();
    if (t < 8) {
        float v = sred2[t];
#pragma unroll
        for (int o = 4; o; o >>= 1) v += __shfl_xor_sync(0xffu, v, o);
        sred2[t] = v;
    }
    __syncthreads();
    float inv = 1.f / sred2[0];
    p[t] = e0*inv; p[t+256] = e1*inv; p[t+512] = e2*inv; p[t+768] = e3*inv;
}

// ---------------- head-average of probabilities -> avg_weights ----------------
__global__ void k_avg(const float* __restrict__ A, float* __restrict__ avg)
{
    size_t idx = (size_t)blockIdx.x * 256 + threadIdx.x;
    if (idx >= (size_t)BDIM * LQ * SK) return;
    int s = idx & (SK - 1);
    int l = (idx >> 10) & (LQ - 1);
    int b = (int)(idx >> 19);
    const float* base = A + ((size_t)b * HDIM) * LQ * SK + (size_t)l * SK + s;
    float acc = 0.f;
#pragma unroll
    for (int h = 0; h < HDIM; h++) acc += base[(size_t)h * LQ * SK];
    avg[idx] = acc * (1.f / HDIM);
}

// ---------------- attn @ V1 / V2, gate, combine -> Comb [L*B, E] ----------------
__global__ void k_av(const float* __restrict__ A, const float* __restrict__ V1,
                     const float* __restrict__ V2, const float* __restrict__ G1,
                     const float* __restrict__ G2, float* __restrict__ Comb)
{
    __shared__ float sA [64][32];    // [l][s]
    __shared__ float sB1[32][64];    // [s][d]
    __shared__ float sB2[32][64];
    const int bh = blockIdx.y;
    const int l0 = blockIdx.x << 6;
    const int tid = threadIdx.x;
    const int tx = tid & 15, ty = tid >> 4;
    const float* Ab  = A  + (size_t)bh * LQ * SK + (size_t)l0 * SK;
    const float* V1b = V1 + (size_t)bh * SK * DHD;
    const float* V2b = V2 + (size_t)bh * SK * DHD;
    float acc1[4][4] = {}, acc2[4][4] = {};
    for (int s0 = 0; s0 < SK; s0 += 32) {
#pragma unroll
        for (int i = 0; i < 2; i++) {
            int f = tid + (i << 8);       // 0..511 float4 slots
            int r = f >> 3, kv = f & 7;
            *(float4*)&sA[r][kv*4] = *(const float4*)(Ab + (size_t)r * SK + s0 + kv*4);
        }
#pragma unroll
        for (int i = 0; i < 2; i++) {
            int f = tid + (i << 8);
            int kk = f >> 4, dv = f & 15;
            *(float4*)&sB1[kk][dv*4] = *(const float4*)(V1b + (size_t)(s0 + kk) * DHD + dv*4);
            *(float4*)&sB2[kk][dv*4] = *(const float4*)(V2b + (size_t)(s0 + kk) * DHD + dv*4);
        }
        __syncthreads();
#pragma unroll 8
        for (int kk = 0; kk < 32; kk++) {
            float a0 = sA[ty*4+0][kk], a1 = sA[ty*4+1][kk];
            float a2 = sA[ty*4+2][kk], a3 = sA[ty*4+3][kk];
            float4 b1 = *(const float4*)&sB1[kk][tx*4];
            float4 b2 = *(const float4*)&sB2[kk][tx*4];
            acc1[0][0]=fmaf(a0,b1.x,acc1[0][0]); acc1[0][1]=fmaf(a0,b1.y,acc1[0][1]); acc1[0][2]=fmaf(a0,b1.z,acc1[0][2]); acc1[0][3]=fmaf(a0,b1.w,acc1[0][3]);
            acc1[1][0]=fmaf(a1,b1.x,acc1[1][0]); acc1[1][1]=fmaf(a1,b1.y,acc1[1][1]); acc1[1][2]=fmaf(a1,b1.z,acc1[1][2]); acc1[1][3]=fmaf(a1,b1.w,acc1[1][3]);
            acc1[2][0]=fmaf(a2,b1.x,acc1[2][0]); acc1[2][1]=fmaf(a2,b1.y,acc1[2][1]); acc1[2][2]=fmaf(a2,b1.z,acc1[2][2]); acc1[2][3]=fmaf(a2,b1.w,acc1[2][3]);
            acc1[3][0]=fmaf(a3,b1.x,acc1[3][0]); acc1[3][1]=fmaf(a3,b1.y,acc1[3][1]); acc1[3][2]=fmaf(a3,b1.z,acc1[3][2]); acc1[3][3]=fmaf(a3,b1.w,acc1[3][3]);
            acc2[0][0]=fmaf(a0,b2.x,acc2[0][0]); acc2[0][1]=fmaf(a0,b2.y,acc2[0][1]); acc2[0][2]=fmaf(a0,b2.z,acc2[0][2]); acc2[0][3]=fmaf(a0,b2.w,acc2[0][3]);
            acc2[1][0]=fmaf(a1,b2.x,acc2[1][0]); acc2[1][1]=fmaf(a1,b2.y,acc2[1][1]); acc2[1][2]=fmaf(a1,b2.z,acc2[1][2]); acc2[1][3]=fmaf(a1,b2.w,acc2[1][3]);
            acc2[2][0]=fmaf(a2,b2.x,acc2[2][0]); acc2[2][1]=fmaf(a2,b2.y,acc2[2][1]); acc2[2][2]=fmaf(a2,b2.z,acc2[2][2]); acc2[2][3]=fmaf(a2,b2.w,acc2[2][3]);
            acc2[3][0]=fmaf(a3,b2.x,acc2[3][0]); acc2[3][1]=fmaf(a3,b2.y,acc2[3][1]); acc2[3][2]=fmaf(a3,b2.z,acc2[3][2]); acc2[3][3]=fmaf(a3,b2.w,acc2[3][3]);
        }
        __syncthreads();
    }
    const int b = bh >> 4, h = bh & 15;
#pragma unroll
    for (int i = 0; i < 4; i++) {
        int l = l0 + ty*4 + i;
        const float* g1r = G1 + ((size_t)bh * LQ + l) * DHD;
        const float* g2r = G2 + ((size_t)bh * LQ + l) * DHD;
#pragma unroll
        for (int j = 0; j < 4; j++) {
            int d = tx*4 + j;
            float c = (acc1[i][j] * g1r[d] + acc2[i][j] * g2r[d]) * 0.5f;
            Comb[((size_t)l * BDIM + b) * EDIM + h * DHD + d] = c;
        }
    }
}

// ---------------- launch ----------------
extern "C" void kernel_launch(void* const* d_in, const int* in_sizes, int n_in,
                              void* d_out, int out_size)
{
    const float* query = (const float*)d_in[0];
    const float* mod1  = (const float*)d_in[1];
    const float* mod2  = (const float*)d_in[2];
    const float* w[8];
    const float* bi[8];
    for (int i = 0; i < 8; i++) {           // q k1 k2 v1 v2 g1 g2 o
        w[i]  = (const float*)d_in[3 + 2*i];
        bi[i] = (const float*)d_in[4 + 2*i];
    }
    float* out = (float*)d_out;
    float* avg_out = out + (size_t)LQ * BDIM * EDIM;

    float *Qh, *K1h, *K2h, *V1h, *V2h, *G1h, *G2h, *ll, *vv, *aa, *va, *Attn, *Comb;
    cudaGetSymbolAddress((void**)&Qh,  g_Qh);
    cudaGetSymbolAddress((void**)&K1h, g_K1h);
    cudaGetSymbolAddress((void**)&K2h, g_K2h);
    cudaGetSymbolAddress((void**)&V1h, g_V1h);
    cudaGetSymbolAddress((void**)&V2h, g_V2h);
    cudaGetSymbolAddress((void**)&G1h, g_G1h);
    cudaGetSymbolAddress((void**)&G2h, g_G2h);
    cudaGetSymbolAddress((void**)&ll,  g_ll);
    cudaGetSymbolAddress((void**)&vv,  g_vv);
    cudaGetSymbolAddress((void**)&aa,  g_aa);
    cudaGetSymbolAddress((void**)&va,  g_va);
    cudaGetSymbolAddress((void**)&Attn, g_Attn);
    cudaGetSymbolAddress((void**)&Comb, g_Comb);

    dim3 blk(256);
    dim3 gq(16, 32);   // E/64 x (L*B)/64
    dim3 gk(16, 64);   // E/64 x (S*B)/64

    k_gemm<<<gq, blk>>>(query, w[0], bi[0], Qh,  2048, LQ, 0.125f, 0);   // q (scaled)
    k_gemm<<<gk, blk>>>(mod1,  w[1], bi[1], K1h, 4096, SK, 1.f, 0);      // k1
    k_gemm<<<gk, blk>>>(mod2,  w[2], bi[2], K2h, 4096, SK, 1.f, 0);      // k2
    k_gemm<<<gk, blk>>>(mod1,  w[3], bi[3], V1h, 4096, SK, 1.f, 0);      // v1
    k_gemm<<<gk, blk>>>(mod2,  w[4], bi[4], V2h, 4096, SK, 1.f, 0);      // v2
    k_gemm<<<gq, blk>>>(query, w[5], bi[5], G1h, 2048, LQ, 1.f, 1);      // gate1
    k_gemm<<<gq, blk>>>(query, w[6], bi[6], G2h, 2048, LQ, 1.f, 1);      // gate2

    k_qstats<<<(BH*LQ*32 + 255)/256, 256>>>(Qh, ll);
    k_kstats<<<(BH*SK*32 + 255)/256, 256>>>(K1h, K2h, vv, aa, va);

    k_logits<<<dim3(SK/64, LQ/64, BH), blk>>>(Qh, K1h, K2h, ll, vv, aa, va, Attn);
    k_softmax<<<BH*LQ, 256>>>(Attn);

    if ((size_t)out_size >= 2ULL * LQ * BDIM * EDIM)
        k_avg<<<(BDIM*LQ*SK + 255)/256, 256>>>(Attn, avg_out);

    k_av<<<dim3(LQ/64, BH), blk>>>(Attn, V1h, V2h, G1h, G2h, Comb);
    k_gemm<<<gq, blk>>>(Comb, w[7], bi[7], out, 2048, LQ, 1.f, 2);       // o proj -> attn_output
}

// round 3
// speedup vs baseline: 2.0790x; 2.0790x over previous
#include <cuda_runtime.h>
#include <cuda_bf16.h>
#include <math.h>
#include <stdint.h>

#define EDIM 1024
#define BDIM 4
#define HDIM 16
#define DHD 64
#define LQ 512
#define SK 1024
#define BH 64   // BDIM*HDIM

__device__ __forceinline__ uint32_t smem_to_u32(const void* smem_ptr) {
    uint32_t addr;
    asm("{ .reg .u64 tmp; cvta.to.shared.u64 tmp, %1; cvt.u32.u64 %0, tmp; }"
        : "=r"(addr) : "l"(smem_ptr));
    return addr;
}

__device__ __forceinline__ void ldm_x4(uint32_t* r, uint32_t addr) {
    asm volatile("ldmatrix.sync.aligned.m8n8.x4.shared.b16 {%0,%1,%2,%3}, [%4];"
        : "=r"(r[0]), "=r"(r[1]), "=r"(r[2]), "=r"(r[3]) : "r"(addr));
}

__device__ __forceinline__ void mma16816(float* d, const uint32_t* a, uint32_t b0, uint32_t b1) {
    asm volatile("mma.sync.aligned.m16n8k16.row.col.f32.bf16.bf16.f32 "
        "{%0,%1,%2,%3}, {%4,%5,%6,%7}, {%8,%9}, {%0,%1,%2,%3};"
        : "+f"(d[0]), "+f"(d[1]), "+f"(d[2]), "+f"(d[3])
        : "r"(a[0]), "r"(a[1]), "r"(a[2]), "r"(a[3]), "r"(b0), "r"(b1));
}

#define CP_ASYNC16(saddr, gptr) \
    asm volatile("cp.async.cg.shared.global [%0], [%1], 16;" :: "r"(saddr), "l"(gptr))
#define CP_COMMIT()  asm volatile("cp.async.commit_group;" ::: "memory")
#define CP_WAIT(N)   asm volatile("cp.async.wait_group %0;" :: "n"(N) : "memory")

// ---------------- scratch (static device globals; no allocation) ----------------
__device__ float g_Qh [BH*LQ*DHD];
__device__ float g_K1h[BH*SK*DHD];
__device__ float g_K2h[BH*SK*DHD];
__device__ float g_V1h[BH*SK*DHD];
__device__ float g_V2h[BH*SK*DHD];
__device__ float g_G1h[BH*LQ*DHD];
__device__ float g_G2h[BH*LQ*DHD];
__device__ float g_ll [BH*LQ];
__device__ float g_vv [BH*SK];
__device__ float g_aa [BH*SK];
__device__ float g_va [BH*SK];
__device__ float g_Attn[BH*LQ*SK];          // 134 MB logits->probs scratch
__device__ float g_Comb[LQ*BDIM*EDIM];      // gated combined output pre o-proj

// bf16 split scratch (hi/lo), all 16B-aligned
__device__ __align__(16) __nv_bfloat16 g_xq_hi[2048*1024];
__device__ __align__(16) __nv_bfloat16 g_xq_lo[2048*1024];
__device__ __align__(16) __nv_bfloat16 g_m1_hi[4096*1024];
__device__ __align__(16) __nv_bfloat16 g_m1_lo[4096*1024];
__device__ __align__(16) __nv_bfloat16 g_m2_hi[4096*1024];
__device__ __align__(16) __nv_bfloat16 g_m2_lo[4096*1024];
__device__ __align__(16) __nv_bfloat16 g_cb_hi[2048*1024];
__device__ __align__(16) __nv_bfloat16 g_cb_lo[2048*1024];
__device__ __align__(16) __nv_bfloat16 g_wt_hi[8*1024*1024];
__device__ __align__(16) __nv_bfloat16 g_wt_lo[8*1024*1024];

// ---------------- fp32 -> bf16 hi/lo split (elementwise) ----------------
__global__ void k_split(const float* __restrict__ x, __nv_bfloat16* __restrict__ hi,
                        __nv_bfloat16* __restrict__ lo, int n4)
{
    int i = blockIdx.x * 256 + threadIdx.x;
    if (i >= n4) return;
    float4 v = ((const float4*)x)[i];
    __nv_bfloat16 h0 = __float2bfloat16(v.x);
    __nv_bfloat16 h1 = __float2bfloat16(v.y);
    __nv_bfloat16 h2 = __float2bfloat16(v.z);
    __nv_bfloat16 h3 = __float2bfloat16(v.w);
    __nv_bfloat16 l0 = __float2bfloat16(v.x - __bfloat162float(h0));
    __nv_bfloat16 l1 = __float2bfloat16(v.y - __bfloat162float(h1));
    __nv_bfloat16 l2 = __float2bfloat16(v.z - __bfloat162float(h2));
    __nv_bfloat16 l3 = __float2bfloat16(v.w - __bfloat162float(h3));
    __nv_bfloat162* hp = (__nv_bfloat162*)(hi + (size_t)i * 4);
    __nv_bfloat162* lp = (__nv_bfloat162*)(lo + (size_t)i * 4);
    hp[0] = __nv_bfloat162(h0, h1); hp[1] = __nv_bfloat162(h2, h3);
    lp[0] = __nv_bfloat162(l0, l1); lp[1] = __nv_bfloat162(l2, l3);
}

// ---------------- W [k][n] -> WT hi/lo [n][k] (transpose + split) ----------------
__global__ void k_wsplit(const float* __restrict__ W, __nv_bfloat16* __restrict__ Thi,
                         __nv_bfloat16* __restrict__ Tlo)
{
    __shared__ float t[32][33];
    const int bx = blockIdx.x << 5;   // n
    const int by = blockIdx.y << 5;   // k
    const int x = threadIdx.x, y = threadIdx.y;   // 32 x 8
#pragma unroll
    for (int i = 0; i < 32; i += 8)
        t[y + i][x] = W[(size_t)(by + y + i) * EDIM + bx + x];
    __syncthreads();
#pragma unroll
    for (int i = 0; i < 32; i += 8) {
        float v = t[x][y + i];                  // = W[by+x][bx+y+i]
        __nv_bfloat16 h = __float2bfloat16(v);
        __nv_bfloat16 l = __float2bfloat16(v - __bfloat162float(h));
        size_t o = (size_t)(bx + y + i) * EDIM + by + x;
        Thi[o] = h; Tlo[o] = l;
    }
}

// ================== warp-MMA bf16x3 GEMM: Y = X @ W + b ==================
// A = X hi/lo [rows,1024] bf16 row-major; B = W^T hi/lo [1024,1024] bf16 (B[n][k]).
// Tile: 128x128, BK=32, 8 warps (each 32m x 64n), cp.async 2-stage pipeline.
// mode 0: head-split layout [BH,npos,DH] (scaled); 1: sigmoid head-split; 2: plain.
#define PADK 40                               // padded K stride (bf16 elems) -> 80B rows
#define TILE_B (128 * PADK * 2)               // 10240 B per tile
#define STAGE_B (4 * TILE_B)                  // Ahi,Alo,Bhi,Blo
#define GM_SMEM (2 * STAGE_B)                 // 81920 B

__global__ void __launch_bounds__(256, 1)
gemm_mma(const __nv_bfloat16* __restrict__ Ahi, const __nv_bfloat16* __restrict__ Alo,
         const __nv_bfloat16* __restrict__ Bhi, const __nv_bfloat16* __restrict__ Blo,
         const float* __restrict__ bias, float* __restrict__ out,
         int npos, float scale, int mode)
{
    extern __shared__ char smem[];
    const uint32_t sb = smem_to_u32(smem);
    const int tid = threadIdx.x;
    const int wid = tid >> 5, lane = tid & 31;
    const int m0 = blockIdx.y << 7, n0 = blockIdx.x << 7;
    const int wm = (wid & 3) << 5;            // warp m offset 0..96
    const int wn = (wid >> 2) << 6;           // warp n offset 0 or 64

    float acc[2][8][4];
#pragma unroll
    for (int i = 0; i < 2; i++)
#pragma unroll
        for (int j = 0; j < 8; j++)
#pragma unroll
            for (int q = 0; q < 4; q++) acc[i][j][q] = 0.f;

    // ---- async stage loader: 2048 16B chunks; tile t: 0=Ahi 1=Alo 2=Bhi 3=Blo ----
#define LOAD_STAGE(s, kb) do { \
    _Pragma("unroll") \
    for (int i = 0; i < 8; i++) { \
        int t = i >> 1; \
        int chunk = ((i & 1) << 8) + tid; \
        int r = chunk >> 2, c = chunk & 3; \
        const __nv_bfloat16* gp = (t == 0) ? Ahi : (t == 1) ? Alo : (t == 2) ? Bhi : Blo; \
        int rowbase = (t < 2) ? m0 : n0; \
        const __nv_bfloat16* g = gp + (((size_t)(rowbase + r)) << 10) + (kb) + (c << 3); \
        uint32_t sa = sb + (uint32_t)(s) * STAGE_B + (uint32_t)t * TILE_B + (uint32_t)(r * PADK + c * 8) * 2u; \
        CP_ASYNC16(sa, g); \
    } \
    CP_COMMIT(); \
} while (0)

    LOAD_STAGE(0, 0);

    for (int it = 0; it < 32; it++) {
        const int s = it & 1;
        if (it + 1 < 32) { LOAD_STAGE(s ^ 1, (it + 1) << 5); CP_WAIT(1); }
        else             { CP_WAIT(0); }
        __syncthreads();

        const uint32_t st = sb + (uint32_t)s * STAGE_B;
#pragma unroll
        for (int kk = 0; kk < 2; kk++) {
            const uint32_t coff = (uint32_t)(kk * 16 + ((lane >> 4) << 3)) * 2u;
            uint32_t ahi[2][4], alo[2][4];
#pragma unroll
            for (int mt = 0; mt < 2; mt++) {
                uint32_t ra = (uint32_t)((wm + mt * 16 + (lane & 15)) * PADK) * 2u + coff;
                ldm_x4(ahi[mt], st + ra);
                ldm_x4(alo[mt], st + TILE_B + ra);
            }
            uint32_t bhi[4][4], blo[4][4];
#pragma unroll
            for (int ng = 0; ng < 4; ng++) {
                uint32_t rb = (uint32_t)((wn + ng * 16 + (lane & 15)) * PADK) * 2u + coff;
                ldm_x4(bhi[ng], st + 2 * TILE_B + rb);
                ldm_x4(blo[ng], st + 3 * TILE_B + rb);
            }
#pragma unroll
            for (int mt = 0; mt < 2; mt++)
#pragma unroll
                for (int nt = 0; nt < 8; nt++) {
                    const int ng = nt >> 1, sel = nt & 1;
                    mma16816(acc[mt][nt], ahi[mt], bhi[ng][sel], bhi[ng][sel + 2]);
                    mma16816(acc[mt][nt], ahi[mt], blo[ng][sel], blo[ng][sel + 2]);
                    mma16816(acc[mt][nt], alo[mt], bhi[ng][sel], bhi[ng][sel + 2]);
                }
        }
        __syncthreads();
    }

    // ---- epilogue ----
    const int qr = lane >> 2, qc = (lane & 3) << 1;
#pragma unroll
    for (int mt = 0; mt < 2; mt++) {
#pragma unroll
        for (int nt = 0; nt < 8; nt++) {
#pragma unroll
            for (int q = 0; q < 4; q++) {
                int row = m0 + wm + mt * 16 + qr + ((q >> 1) << 3);
                int col = n0 + wn + nt * 8 + qc + (q & 1);
                float v = (acc[mt][nt][q] + bias[col]) * scale;
                if (mode == 1) v = 1.f / (1.f + expf(-v));
                if (mode == 2) {
                    out[(size_t)row * EDIM + col] = v;
                } else {
                    int pos = row >> 2;              // B = 4
                    int b = row & 3;
                    int h = col >> 6, d = col & 63;
                    out[((size_t)(b * HDIM + h) * npos + pos) * DHD + d] = v;
                }
            }
        }
    }
#undef LOAD_STAGE
}

// ---------------- per-row stats ----------------
__global__ void k_qstats(const float* __restrict__ Q, float* __restrict__ ll)
{
    int gw = (blockIdx.x * blockDim.x + threadIdx.x) >> 5;
    int lane = threadIdx.x & 31;
    if (gw >= BH*LQ) return;
    const float* q = Q + (size_t)gw * DHD;
    float a0 = q[lane], a1 = q[lane + 32];
    float s = a0*a0 + a1*a1;
#pragma unroll
    for (int o = 16; o; o >>= 1) s += __shfl_xor_sync(0xffffffffu, s, o);
    if (!lane) ll[gw] = s;
}

__global__ void k_kstats(const float* __restrict__ K1, const float* __restrict__ K2,
                         float* __restrict__ vv, float* __restrict__ aa, float* __restrict__ va)
{
    int gw = (blockIdx.x * blockDim.x + threadIdx.x) >> 5;
    int lane = threadIdx.x & 31;
    if (gw >= BH*SK) return;
    const float* a = K1 + (size_t)gw * DHD;
    const float* b = K2 + (size_t)gw * DHD;
    float a0 = a[lane], a1 = a[lane + 32];
    float b0 = b[lane], b1 = b[lane + 32];
    float svv = a0*a0 + a1*a1, saa = b0*b0 + b1*b1, sva = a0*b0 + a1*b1;
#pragma unroll
    for (int o = 16; o; o >>= 1) {
        svv += __shfl_xor_sync(0xffffffffu, svv, o);
        saa += __shfl_xor_sync(0xffffffffu, saa, o);
        sva += __shfl_xor_sync(0xffffffffu, sva, o);
    }
    if (!lane) { vv[gw] = svv; aa[gw] = saa; va[gw] = sva; }
}

// ---------------- logits: lv + la - 1.5*sqrt(gram det) -> Attn ----------------
__global__ void k_logits(const float* __restrict__ Qh, const float* __restrict__ K1h,
                         const float* __restrict__ K2h, const float* __restrict__ ll,
                         const float* __restrict__ vv, const float* __restrict__ aa,
                         const float* __restrict__ va, float* __restrict__ A)
{
    __shared__ float sQ [64][64];
    __shared__ float sK1[64][64];
    __shared__ float sK2[64][64];
    const int bh = blockIdx.z;
    const int l0 = blockIdx.y << 6;
    const int s0 = blockIdx.x << 6;
    const int tid = threadIdx.x;
    const float* qb  = Qh  + ((size_t)bh * LQ + l0) * DHD;
    const float* k1b = K1h + ((size_t)bh * SK + s0) * DHD;
    const float* k2b = K2h + ((size_t)bh * SK + s0) * DHD;
#pragma unroll
    for (int i = 0; i < 4; i++) {
        int f = tid + (i << 8);
        int r = f & 63;
        int dv = f >> 6;
        float4 q4 = *(const float4*)(qb + (size_t)r * DHD + dv*4);
        sQ[dv*4+0][r] = q4.x; sQ[dv*4+1][r] = q4.y; sQ[dv*4+2][r] = q4.z; sQ[dv*4+3][r] = q4.w;
        float4 u4 = *(const float4*)(k1b + (size_t)r * DHD + dv*4);
        sK1[dv*4+0][r] = u4.x; sK1[dv*4+1][r] = u4.y; sK1[dv*4+2][r] = u4.z; sK1[dv*4+3][r] = u4.w;
        float4 w4 = *(const float4*)(k2b + (size_t)r * DHD + dv*4);
        sK2[dv*4+0][r] = w4.x; sK2[dv*4+1][r] = w4.y; sK2[dv*4+2][r] = w4.z; sK2[dv*4+3][r] = w4.w;
    }
    __syncthreads();
    const int tx = tid & 15, ty = tid >> 4;
    float lv[4][4] = {}, la[4][4] = {};
#pragma unroll 8
    for (int d = 0; d < 64; d++) {
        float a0 = sQ[d][ty*4+0], a1 = sQ[d][ty*4+1];
        float a2 = sQ[d][ty*4+2], a3 = sQ[d][ty*4+3];
        float4 b1 = *(const float4*)&sK1[d][tx*4];
        float4 b2 = *(const float4*)&sK2[d][tx*4];
        lv[0][0]=fmaf(a0,b1.x,lv[0][0]); lv[0][1]=fmaf(a0,b1.y,lv[0][1]); lv[0][2]=fmaf(a0,b1.z,lv[0][2]); lv[0][3]=fmaf(a0,b1.w,lv[0][3]);
        lv[1][0]=fmaf(a1,b1.x,lv[1][0]); lv[1][1]=fmaf(a1,b1.y,lv[1][1]); lv[1][2]=fmaf(a1,b1.z,lv[1][2]); lv[1][3]=fmaf(a1,b1.w,lv[1][3]);
        lv[2][0]=fmaf(a2,b1.x,lv[2][0]); lv[2][1]=fmaf(a2,b1.y,lv[2][1]); lv[2][2]=fmaf(a2,b1.z,lv[2][2]); lv[2][3]=fmaf(a2,b1.w,lv[2][3]);
        lv[3][0]=fmaf(a3,b1.x,lv[3][0]); lv[3][1]=fmaf(a3,b1.y,lv[3][1]); lv[3][2]=fmaf(a3,b1.z,lv[3][2]); lv[3][3]=fmaf(a3,b1.w,lv[3][3]);
        la[0][0]=fmaf(a0,b2.x,la[0][0]); la[0][1]=fmaf(a0,b2.y,la[0][1]); la[0][2]=fmaf(a0,b2.z,la[0][2]); la[0][3]=fmaf(a0,b2.w,la[0][3]);
        la[1][0]=fmaf(a1,b2.x,la[1][0]); la[1][1]=fmaf(a1,b2.y,la[1][1]); la[1][2]=fmaf(a1,b2.z,la[1][2]); la[1][3]=fmaf(a1,b2.w,la[1][3]);
        la[2][0]=fmaf(a2,b2.x,la[2][0]); la[2][1]=fmaf(a2,b2.y,la[2][1]); la[2][2]=fmaf(a2,b2.z,la[2][2]); la[2][3]=fmaf(a2,b2.w,la[2][3]);
        la[3][0]=fmaf(a3,b2.x,la[3][0]); la[3][1]=fmaf(a3,b2.y,la[3][1]); la[3][2]=fmaf(a3,b2.z,la[3][2]); la[3][3]=fmaf(a3,b2.w,la[3][3]);
    }
    float llr[4], vvc[4], aac[4], vac[4];
#pragma unroll
    for (int i = 0; i < 4; i++) llr[i] = ll[bh*LQ + l0 + ty*4 + i];
#pragma unroll
    for (int j = 0; j < 4; j++) {
        int c = bh*SK + s0 + tx*4 + j;
        vvc[j] = vv[c]; aac[j] = aa[c]; vac[j] = va[c];
    }
    float* outp = A + (size_t)bh * LQ * SK;
#pragma unroll
    for (int i = 0; i < 4; i++) {
        int row = l0 + ty*4 + i;
        float4 o4;
        float res[4];
#pragma unroll
        for (int j = 0; j < 4; j++) {
            float LV = lv[i][j], LA = la[i][j];
            float det = llr[i] * (vvc[j]*aac[j] - vac[j]*vac[j])
                      - LV * (LV*aac[j] - LA*vac[j])
                      + LA * (LV*vac[j] - LA*vvc[j]);
            det = fmaxf(det, 1e-8f);
            res[j] = LV + LA - 1.5f * sqrtf(det);
        }
        o4.x = res[0]; o4.y = res[1]; o4.z = res[2]; o4.w = res[3];
        *(float4*)(outp + (size_t)row * SK + s0 + tx*4) = o4;
    }
}

// ---------------- softmax over S (in place) ----------------
__global__ void k_softmax(float* __restrict__ A)
{
    const int row = blockIdx.x;
    float* p = A + (size_t)row * SK;
    const int t = threadIdx.x;
    float x0 = p[t], x1 = p[t+256], x2 = p[t+512], x3 = p[t+768];
    float m = fmaxf(fmaxf(x0, x1), fmaxf(x2, x3));
    __shared__ float sred[8];
#pragma unroll
    for (int o = 16; o; o >>= 1) m = fmaxf(m, __shfl_xor_sync(0xffffffffu, m, o));
    if ((t & 31) == 0) sred[t >> 5] = m;
    __syncthreads();
    if (t < 8) {
        float v = sred[t];
#pragma unroll
        for (int o = 4; o; o >>= 1) v = fmaxf(v, __shfl_xor_sync(0xffu, v, o));
        sred[t] = v;
    }
    __syncthreads();
    m = sred[0];
    float e0 = expf(x0 - m), e1 = expf(x1 - m), e2 = expf(x2 - m), e3 = expf(x3 - m);
    float s = e0 + e1 + e2 + e3;
#pragma unroll
    for (int o = 16; o; o >>= 1) s += __shfl_xor_sync(0xffffffffu, s, o);
    __shared__ float sred2[8];
    if ((t & 31) == 0) sred2[t >> 5] = s;
    __syncthreads();
    if (t < 8) {
        float v = sred2[t];
#pragma unroll
        for (int o = 4; o; o >>= 1) v += __shfl_xor_sync(0xffu, v, o);
        sred2[t] = v;
    }
    __syncthreads();
    float inv = 1.f / sred2[0];
    p[t] = e0*inv; p[t+256] = e1*inv; p[t+512] = e2*inv; p[t+768] = e3*inv;
}

// ---------------- head-average of probabilities -> avg_weights ----------------
__global__ void k_avg(const float* __restrict__ A, float* __restrict__ avg)
{
    size_t idx = (size_t)blockIdx.x * 256 + threadIdx.x;
    if (idx >= (size_t)BDIM * LQ * SK) return;
    int s = idx & (SK - 1);
    int l = (idx >> 10) & (LQ - 1);
    int b = (int)(idx >> 19);
    const float* base = A + ((size_t)b * HDIM) * LQ * SK + (size_t)l * SK + s;
    float acc = 0.f;
#pragma unroll
    for (int h = 0; h < HDIM; h++) acc += base[(size_t)h * LQ * SK];
    avg[idx] = acc * (1.f / HDIM);
}

// ---------------- attn @ V1 / V2, gate, combine -> Comb [L*B, E] ----------------
__global__ void k_av(const float* __restrict__ A, const float* __restrict__ V1,
                     const float* __restrict__ V2, const float* __restrict__ G1,
                     const float* __restrict__ G2, float* __restrict__ Comb)
{
    __shared__ float sA [64][32];
    __shared__ float sB1[32][64];
    __shared__ float sB2[32][64];
    const int bh = blockIdx.y;
    const int l0 = blockIdx.x << 6;
    const int tid = threadIdx.x;
    const int tx = tid & 15, ty = tid >> 4;
    const float* Ab  = A  + (size_t)bh * LQ * SK + (size_t)l0 * SK;
    const float* V1b = V1 + (size_t)bh * SK * DHD;
    const float* V2b = V2 + (size_t)bh * SK * DHD;
    float acc1[4][4] = {}, acc2[4][4] = {};
    for (int s0 = 0; s0 < SK; s0 += 32) {
#pragma unroll
        for (int i = 0; i < 2; i++) {
            int f = tid + (i << 8);
            int r = f >> 3, kv = f & 7;
            *(float4*)&sA[r][kv*4] = *(const float4*)(Ab + (size_t)r * SK + s0 + kv*4);
        }
#pragma unroll
        for (int i = 0; i < 2; i++) {
            int f = tid + (i << 8);
            int kk = f >> 4, dv = f & 15;
            *(float4*)&sB1[kk][dv*4] = *(const float4*)(V1b + (size_t)(s0 + kk) * DHD + dv*4);
            *(float4*)&sB2[kk][dv*4] = *(const float4*)(V2b + (size_t)(s0 + kk) * DHD + dv*4);
        }
        __syncthreads();
#pragma unroll 8
        for (int kk = 0; kk < 32; kk++) {
            float a0 = sA[ty*4+0][kk], a1 = sA[ty*4+1][kk];
            float a2 = sA[ty*4+2][kk], a3 = sA[ty*4+3][kk];
            float4 b1 = *(const float4*)&sB1[kk][tx*4];
            float4 b2 = *(const float4*)&sB2[kk][tx*4];
            acc1[0][0]=fmaf(a0,b1.x,acc1[0][0]); acc1[0][1]=fmaf(a0,b1.y,acc1[0][1]); acc1[0][2]=fmaf(a0,b1.z,acc1[0][2]); acc1[0][3]=fmaf(a0,b1.w,acc1[0][3]);
            acc1[1][0]=fmaf(a1,b1.x,acc1[1][0]); acc1[1][1]=fmaf(a1,b1.y,acc1[1][1]); acc1[1][2]=fmaf(a1,b1.z,acc1[1][2]); acc1[1][3]=fmaf(a1,b1.w,acc1[1][3]);
            acc1[2][0]=fmaf(a2,b1.x,acc1[2][0]); acc1[2][1]=fmaf(a2,b1.y,acc1[2][1]); acc1[2][2]=fmaf(a2,b1.z,acc1[2][2]); acc1[2][3]=fmaf(a2,b1.w,acc1[2][3]);
            acc1[3][0]=fmaf(a3,b1.x,acc1[3][0]); acc1[3][1]=fmaf(a3,b1.y,acc1[3][1]); acc1[3][2]=fmaf(a3,b1.z,acc1[3][2]); acc1[3][3]=fmaf(a3,b1.w,acc1[3][3]);
            acc2[0][0]=fmaf(a0,b2.x,acc2[0][0]); acc2[0][1]=fmaf(a0,b2.y,acc2[0][1]); acc2[0][2]=fmaf(a0,b2.z,acc2[0][2]); acc2[0][3]=fmaf(a0,b2.w,acc2[0][3]);
            acc2[1][0]=fmaf(a1,b2.x,acc2[1][0]); acc2[1][1]=fmaf(a1,b2.y,acc2[1][1]); acc2[1][2]=fmaf(a1,b2.z,acc2[1][2]); acc2[1][3]=fmaf(a1,b2.w,acc2[1][3]);
            acc2[2][0]=fmaf(a2,b2.x,acc2[2][0]); acc2[2][1]=fmaf(a2,b2.y,acc2[2][1]); acc2[2][2]=fmaf(a2,b2.z,acc2[2][2]); acc2[2][3]=fmaf(a2,b2.w,acc2[2][3]);
            acc2[3][0]=fmaf(a3,b2.x,acc2[3][0]); acc2[3][1]=fmaf(a3,b2.y,acc2[3][1]); acc2[3][2]=fmaf(a3,b2.z,acc2[3][2]); acc2[3][3]=fmaf(a3,b2.w,acc2[3][3]);
        }
        __syncthreads();
    }
    const int b = bh >> 4, h = bh & 15;
#pragma unroll
    for (int i = 0; i < 4; i++) {
        int l = l0 + ty*4 + i;
        const float* g1r = G1 + ((size_t)bh * LQ + l) * DHD;
        const float* g2r = G2 + ((size_t)bh * LQ + l) * DHD;
#pragma unroll
        for (int j = 0; j < 4; j++) {
            int d = tx*4 + j;
            float c = (acc1[i][j] * g1r[d] + acc2[i][j] * g2r[d]) * 0.5f;
            Comb[((size_t)l * BDIM + b) * EDIM + h * DHD + d] = c;
        }
    }
}

// ---------------- launch ----------------
extern "C" void kernel_launch(void* const* d_in, const int* in_sizes, int n_in,
                              void* d_out, int out_size)
{
    const float* query = (const float*)d_in[0];
    const float* mod1  = (const float*)d_in[1];
    const float* mod2  = (const float*)d_in[2];
    const float* w[8];
    const float* bi[8];
    for (int i = 0; i < 8; i++) {           // q k1 k2 v1 v2 g1 g2 o
        w[i]  = (const float*)d_in[3 + 2*i];
        bi[i] = (const float*)d_in[4 + 2*i];
    }
    float* out = (float*)d_out;
    float* avg_out = out + (size_t)LQ * BDIM * EDIM;

    float *Qh, *K1h, *K2h, *V1h, *V2h, *G1h, *G2h, *ll, *vv, *aa, *va, *Attn, *Comb;
    cudaGetSymbolAddress((void**)&Qh,  g_Qh);
    cudaGetSymbolAddress((void**)&K1h, g_K1h);
    cudaGetSymbolAddress((void**)&K2h, g_K2h);
    cudaGetSymbolAddress((void**)&V1h, g_V1h);
    cudaGetSymbolAddress((void**)&V2h, g_V2h);
    cudaGetSymbolAddress((void**)&G1h, g_G1h);
    cudaGetSymbolAddress((void**)&G2h, g_G2h);
    cudaGetSymbolAddress((void**)&ll,  g_ll);
    cudaGetSymbolAddress((void**)&vv,  g_vv);
    cudaGetSymbolAddress((void**)&aa,  g_aa);
    cudaGetSymbolAddress((void**)&va,  g_va);
    cudaGetSymbolAddress((void**)&Attn, g_Attn);
    cudaGetSymbolAddress((void**)&Comb, g_Comb);

    __nv_bfloat16 *xq_hi, *xq_lo, *m1_hi, *m1_lo, *m2_hi, *m2_lo, *cb_hi, *cb_lo, *wt_hi, *wt_lo;
    cudaGetSymbolAddress((void**)&xq_hi, g_xq_hi);
    cudaGetSymbolAddress((void**)&xq_lo, g_xq_lo);
    cudaGetSymbolAddress((void**)&m1_hi, g_m1_hi);
    cudaGetSymbolAddress((void**)&m1_lo, g_m1_lo);
    cudaGetSymbolAddress((void**)&m2_hi, g_m2_hi);
    cudaGetSymbolAddress((void**)&m2_lo, g_m2_lo);
    cudaGetSymbolAddress((void**)&cb_hi, g_cb_hi);
    cudaGetSymbolAddress((void**)&cb_lo, g_cb_lo);
    cudaGetSymbolAddress((void**)&wt_hi, g_wt_hi);
    cudaGetSymbolAddress((void**)&wt_lo, g_wt_lo);

    cudaFuncSetAttribute(gemm_mma, cudaFuncAttributeMaxDynamicSharedMemorySize, GM_SMEM);

    // ---- split inputs to bf16 hi/lo ----
    k_split<<<2048, 256>>>(query, xq_hi, xq_lo, 2048*1024/4);
    k_split<<<4096, 256>>>(mod1,  m1_hi, m1_lo, 4096*1024/4);
    k_split<<<4096, 256>>>(mod2,  m2_hi, m2_lo, 4096*1024/4);
    // ---- transpose + split weights ----
    dim3 wgrid(32, 32), wblk(32, 8);
    for (int i = 0; i < 8; i++)
        k_wsplit<<<wgrid, wblk>>>(w[i], wt_hi + (size_t)i*1024*1024, wt_lo + (size_t)i*1024*1024);

    // ---- projections via bf16x3 warp-MMA ----
    dim3 gq(8, 16);   // 2048 rows
    dim3 gk(8, 32);   // 4096 rows
    size_t WSZ = (size_t)1024*1024;
    gemm_mma<<<gq, 256, GM_SMEM>>>(xq_hi, xq_lo, wt_hi + 0*WSZ, wt_lo + 0*WSZ, bi[0], Qh,  LQ, 0.125f, 0);
    gemm_mma<<<gk, 256, GM_SMEM>>>(m1_hi, m1_lo, wt_hi + 1*WSZ, wt_lo + 1*WSZ, bi[1], K1h, SK, 1.f,    0);
    gemm_mma<<<gk, 256, GM_SMEM>>>(m2_hi, m2_lo, wt_hi + 2*WSZ, wt_lo + 2*WSZ, bi[2], K2h, SK, 1.f,    0);
    gemm_mma<<<gk, 256, GM_SMEM>>>(m1_hi, m1_lo, wt_hi + 3*WSZ, wt_lo + 3*WSZ, bi[3], V1h, SK, 1.f,    0);
    gemm_mma<<<gk, 256, GM_SMEM>>>(m2_hi, m2_lo, wt_hi + 4*WSZ, wt_lo + 4*WSZ, bi[4], V2h, SK, 1.f,    0);
    gemm_mma<<<gq, 256, GM_SMEM>>>(xq_hi, xq_lo, wt_hi + 5*WSZ, wt_lo + 5*WSZ, bi[5], G1h, LQ, 1.f,    1);
    gemm_mma<<<gq, 256, GM_SMEM>>>(xq_hi, xq_lo, wt_hi + 6*WSZ, wt_lo + 6*WSZ, bi[6], G2h, LQ, 1.f,    1);

    // ---- attention (fp32) ----
    k_qstats<<<(BH*LQ*32 + 255)/256, 256>>>(Qh, ll);
    k_kstats<<<(BH*SK*32 + 255)/256, 256>>>(K1h, K2h, vv, aa, va);

    k_logits<<<dim3(SK/64, LQ/64, BH), 256>>>(Qh, K1h, K2h, ll, vv, aa, va, Attn);
    k_softmax<<<BH*LQ, 256>>>(Attn);

    if ((size_t)out_size >= 2ULL * LQ * BDIM * EDIM)
        k_avg<<<(BDIM*LQ*SK + 255)/256, 256>>>(Attn, avg_out);

    k_av<<<dim3(LQ/64, BH), 256>>>(Attn, V1h, V2h, G1h, G2h, Comb);

    // ---- output projection ----
    k_split<<<2048, 256>>>(Comb, cb_hi, cb_lo, 2048*1024/4);
    gemm_mma<<<gq, 256, GM_SMEM>>>(cb_hi, cb_lo, wt_hi + 7*WSZ, wt_lo + 7*WSZ, bi[7], out, LQ, 1.f, 2);
}

// round 4
// speedup vs baseline: 2.6645x; 1.2816x over previous
#include <cuda_runtime.h>
#include <cuda_bf16.h>
#include <math.h>
#include <stdint.h>

#define EDIM 1024
#define BDIM 4
#define HDIM 16
#define DHD 64
#define LQ 512
#define SK 1024
#define BH 64   // BDIM*HDIM

// ======================= helpers =======================
__device__ __forceinline__ uint32_t smem_to_u32(const void* smem_ptr) {
    uint32_t addr;
    asm("{ .reg .u64 tmp; cvta.to.shared.u64 tmp, %1; cvt.u32.u64 %0, tmp; }"
        : "=r"(addr) : "l"(smem_ptr));
    return addr;
}
__device__ __forceinline__ void ldm_x4(uint32_t* r, uint32_t addr) {
    asm volatile("ldmatrix.sync.aligned.m8n8.x4.shared.b16 {%0,%1,%2,%3}, [%4];"
        : "=r"(r[0]), "=r"(r[1]), "=r"(r[2]), "=r"(r[3]) : "r"(addr));
}
__device__ __forceinline__ void ldm_x4_t(uint32_t* r, uint32_t addr) {
    asm volatile("ldmatrix.sync.aligned.m8n8.x4.trans.shared.b16 {%0,%1,%2,%3}, [%4];"
        : "=r"(r[0]), "=r"(r[1]), "=r"(r[2]), "=r"(r[3]) : "r"(addr));
}
__device__ __forceinline__ void mma16816(float* d, const uint32_t* a, uint32_t b0, uint32_t b1) {
    asm volatile("mma.sync.aligned.m16n8k16.row.col.f32.bf16.bf16.f32 "
        "{%0,%1,%2,%3}, {%4,%5,%6,%7}, {%8,%9}, {%0,%1,%2,%3};"
        : "+f"(d[0]), "+f"(d[1]), "+f"(d[2]), "+f"(d[3])
        : "r"(a[0]), "r"(a[1]), "r"(a[2]), "r"(a[3]), "r"(b0), "r"(b1));
}
#define CP_ASYNC16(saddr, gptr) \
    asm volatile("cp.async.cg.shared.global [%0], [%1], 16;" :: "r"(saddr), "l"(gptr))
#define CP_COMMIT()  asm volatile("cp.async.commit_group;" ::: "memory")
#define CP_WAIT(N)   asm volatile("cp.async.wait_group %0;" :: "n"(N) : "memory")

// ---- MUFU-free math (FFMA/ALU only) ----
__device__ __forceinline__ float fast_sqrt(float x) {
    float r = __int_as_float(0x5f3759df - (__float_as_int(x) >> 1));
    r = r * fmaf(-0.5f * x * r, r, 1.5f);
    r = r * fmaf(-0.5f * x * r, r, 1.5f);
    r = r * fmaf(-0.5f * x * r, r, 1.5f);
    return x * r;
}
__device__ __forceinline__ float fast_exp(float x) {
    float y = x * 1.44269504f;
    y = fmaxf(fminf(y, 126.0f), -125.0f);
    float t = y + 12582912.f;                       // 1.5 * 2^23 round trick
    int n = __float_as_int(t) - 0x4B400000;
    float f = y - (t - 12582912.f);                 // f in [-0.5, 0.5]
    float p = 1.33335581e-3f;
    p = fmaf(p, f, 9.61812910e-3f);
    p = fmaf(p, f, 5.55041086e-2f);
    p = fmaf(p, f, 2.40226507e-1f);
    p = fmaf(p, f, 6.93147181e-1f);
    p = fmaf(p, f, 1.0f);
    return __int_as_float(__float_as_int(p) + (n << 23));
}
__device__ __forceinline__ float fast_rcp(float x) {   // x > 0
    float r = __int_as_float(0x7EF311C3 - __float_as_int(x));
    r = r * (2.0f - x * r);
    r = r * (2.0f - x * r);
    r = r * (2.0f - x * r);
    return r;
}
__device__ __forceinline__ float fast_sigmoid(float x) {
    return fast_rcp(1.0f + fast_exp(-x));
}

// ---------------- scratch (static device globals; no allocation) ----------------
__device__ float g_G1h[BH*LQ*DHD];
__device__ float g_G2h[BH*LQ*DHD];
__device__ float g_ll [BH*LQ];
__device__ float g_vv [BH*SK];
__device__ float g_aa [BH*SK];
__device__ float g_va [BH*SK];
__device__ float g_Attn[BH*LQ*SK];          // logits (fp32)

// head-layout bf16 hi/lo projections
__device__ __align__(16) __nv_bfloat16 g_q_hi [BH*LQ*DHD];
__device__ __align__(16) __nv_bfloat16 g_q_lo [BH*LQ*DHD];
__device__ __align__(16) __nv_bfloat16 g_k1_hi[BH*SK*DHD];
__device__ __align__(16) __nv_bfloat16 g_k1_lo[BH*SK*DHD];
__device__ __align__(16) __nv_bfloat16 g_k2_hi[BH*SK*DHD];
__device__ __align__(16) __nv_bfloat16 g_k2_lo[BH*SK*DHD];
__device__ __align__(16) __nv_bfloat16 g_v1_hi[BH*SK*DHD];
__device__ __align__(16) __nv_bfloat16 g_v1_lo[BH*SK*DHD];
__device__ __align__(16) __nv_bfloat16 g_v2_hi[BH*SK*DHD];
__device__ __align__(16) __nv_bfloat16 g_v2_lo[BH*SK*DHD];
// attention probs bf16 hi/lo
__device__ __align__(16) __nv_bfloat16 g_at_hi[BH*LQ*SK];
__device__ __align__(16) __nv_bfloat16 g_at_lo[BH*LQ*SK];
// input splits
__device__ __align__(16) __nv_bfloat16 g_xq_hi[2048*1024];
__device__ __align__(16) __nv_bfloat16 g_xq_lo[2048*1024];
__device__ __align__(16) __nv_bfloat16 g_m1_hi[4096*1024];
__device__ __align__(16) __nv_bfloat16 g_m1_lo[4096*1024];
__device__ __align__(16) __nv_bfloat16 g_m2_hi[4096*1024];
__device__ __align__(16) __nv_bfloat16 g_m2_lo[4096*1024];
__device__ __align__(16) __nv_bfloat16 g_cb_hi[2048*1024];
__device__ __align__(16) __nv_bfloat16 g_cb_lo[2048*1024];
__device__ __align__(16) __nv_bfloat16 g_wt_hi[8*1024*1024];
__device__ __align__(16) __nv_bfloat16 g_wt_lo[8*1024*1024];

// ---------------- fused fp32 -> bf16 hi/lo split for all 3 inputs ----------------
__global__ void k_split_all(const float* __restrict__ q, const float* __restrict__ m1,
                            const float* __restrict__ m2,
                            __nv_bfloat16* __restrict__ qhi, __nv_bfloat16* __restrict__ qlo,
                            __nv_bfloat16* __restrict__ m1hi, __nv_bfloat16* __restrict__ m1lo,
                            __nv_bfloat16* __restrict__ m2hi, __nv_bfloat16* __restrict__ m2lo)
{
    int i = blockIdx.x * 256 + threadIdx.x;      // float4 index, 2.5M total
    const float* src; __nv_bfloat16 *hi, *lo; int off;
    if (i < 512*1024)        { src = q;  hi = qhi;  lo = qlo;  off = i; }
    else if (i < 1536*1024)  { src = m1; hi = m1hi; lo = m1lo; off = i - 512*1024; }
    else                     { src = m2; hi = m2hi; lo = m2lo; off = i - 1536*1024; }
    float4 v = ((const float4*)src)[off];
    __nv_bfloat16 h0 = __float2bfloat16(v.x), h1 = __float2bfloat16(v.y);
    __nv_bfloat16 h2 = __float2bfloat16(v.z), h3 = __float2bfloat16(v.w);
    __nv_bfloat16 l0 = __float2bfloat16(v.x - __bfloat162float(h0));
    __nv_bfloat16 l1 = __float2bfloat16(v.y - __bfloat162float(h1));
    __nv_bfloat16 l2 = __float2bfloat16(v.z - __bfloat162float(h2));
    __nv_bfloat16 l3 = __float2bfloat16(v.w - __bfloat162float(h3));
    __nv_bfloat162* hp = (__nv_bfloat162*)(hi + (size_t)off * 4);
    __nv_bfloat162* lp = (__nv_bfloat162*)(lo + (size_t)off * 4);
    hp[0] = __nv_bfloat162(h0, h1); hp[1] = __nv_bfloat162(h2, h3);
    lp[0] = __nv_bfloat162(l0, l1); lp[1] = __nv_bfloat162(l2, l3);
}

// ---------------- all 8 weights: W [k][n] -> WT hi/lo [n][k] ----------------
struct WPtrs { const float* p[8]; };
__global__ void k_wsplit_all(WPtrs wp, __nv_bfloat16* __restrict__ ThiAll,
                             __nv_bfloat16* __restrict__ TloAll)
{
    __shared__ float t[32][33];
    const int wi = blockIdx.z;
    const float* W = wp.p[wi];
    __nv_bfloat16* Thi = ThiAll + (size_t)wi * 1024 * 1024;
    __nv_bfloat16* Tlo = TloAll + (size_t)wi * 1024 * 1024;
    const int bx = blockIdx.x << 5;   // n
    const int by = blockIdx.y << 5;   // k
    const int x = threadIdx.x, y = threadIdx.y;   // 32 x 8
#pragma unroll
    for (int i = 0; i < 32; i += 8)
        t[y + i][x] = W[(size_t)(by + y + i) * EDIM + bx + x];
    __syncthreads();
#pragma unroll
    for (int i = 0; i < 32; i += 8) {
        float v = t[x][y + i];
        __nv_bfloat16 h = __float2bfloat16(v);
        __nv_bfloat16 l = __float2bfloat16(v - __bfloat162float(h));
        size_t o = (size_t)(bx + y + i) * EDIM + by + x;
        Thi[o] = h; Tlo[o] = l;
    }
}

// ================== warp-MMA bf16x3 GEMM: Y = X @ W + b ==================
// mode 0: head-split bf16 hi/lo [BH,npos,DH] (scaled); 1: sigmoid fp32 head-split;
// 2: plain fp32 [rows,E].
#define PADK 40
#define TILE_B (128 * PADK * 2)
#define STAGE_B (4 * TILE_B)
#define GM_SMEM (2 * STAGE_B)

__global__ void __launch_bounds__(256, 1)
gemm_mma(const __nv_bfloat16* __restrict__ Ahi, const __nv_bfloat16* __restrict__ Alo,
         const __nv_bfloat16* __restrict__ Bhi, const __nv_bfloat16* __restrict__ Blo,
         const float* __restrict__ bias, float* __restrict__ outF,
         __nv_bfloat16* __restrict__ outHi, __nv_bfloat16* __restrict__ outLo,
         int npos, float scale, int mode)
{
    extern __shared__ char smem[];
    const uint32_t sb = smem_to_u32(smem);
    const int tid = threadIdx.x;
    const int wid = tid >> 5, lane = tid & 31;
    const int m0 = blockIdx.y << 7, n0 = blockIdx.x << 7;
    const int wm = (wid & 3) << 5;
    const int wn = (wid >> 2) << 6;

    float acc[2][8][4];
#pragma unroll
    for (int i = 0; i < 2; i++)
#pragma unroll
        for (int j = 0; j < 8; j++)
#pragma unroll
            for (int q = 0; q < 4; q++) acc[i][j][q] = 0.f;

#define LOAD_STAGE(s, kb) do { \
    _Pragma("unroll") \
    for (int i = 0; i < 8; i++) { \
        int t = i >> 1; \
        int chunk = ((i & 1) << 8) + tid; \
        int r = chunk >> 2, c = chunk & 3; \
        const __nv_bfloat16* gp = (t == 0) ? Ahi : (t == 1) ? Alo : (t == 2) ? Bhi : Blo; \
        int rowbase = (t < 2) ? m0 : n0; \
        const __nv_bfloat16* g = gp + (((size_t)(rowbase + r)) << 10) + (kb) + (c << 3); \
        uint32_t sa = sb + (uint32_t)(s) * STAGE_B + (uint32_t)t * TILE_B + (uint32_t)(r * PADK + c * 8) * 2u; \
        CP_ASYNC16(sa, g); \
    } \
    CP_COMMIT(); \
} while (0)

    LOAD_STAGE(0, 0);

    for (int it = 0; it < 32; it++) {
        const int s = it & 1;
        if (it + 1 < 32) { LOAD_STAGE(s ^ 1, (it + 1) << 5); CP_WAIT(1); }
        else             { CP_WAIT(0); }
        __syncthreads();

        const uint32_t st = sb + (uint32_t)s * STAGE_B;
#pragma unroll
        for (int kk = 0; kk < 2; kk++) {
            const uint32_t coff = (uint32_t)(kk * 16 + ((lane >> 4) << 3)) * 2u;
            uint32_t ahi[2][4], alo[2][4];
#pragma unroll
            for (int mt = 0; mt < 2; mt++) {
                uint32_t ra = (uint32_t)((wm + mt * 16 + (lane & 15)) * PADK) * 2u + coff;
                ldm_x4(ahi[mt], st + ra);
                ldm_x4(alo[mt], st + TILE_B + ra);
            }
            uint32_t bhi[4][4], blo[4][4];
#pragma unroll
            for (int ng = 0; ng < 4; ng++) {
                uint32_t rb = (uint32_t)((wn + ng * 16 + (lane & 15)) * PADK) * 2u + coff;
                ldm_x4(bhi[ng], st + 2 * TILE_B + rb);
                ldm_x4(blo[ng], st + 3 * TILE_B + rb);
            }
#pragma unroll
            for (int mt = 0; mt < 2; mt++)
#pragma unroll
                for (int nt = 0; nt < 8; nt++) {
                    const int ng = nt >> 1, sel = nt & 1;
                    mma16816(acc[mt][nt], ahi[mt], bhi[ng][sel], bhi[ng][sel + 2]);
                    mma16816(acc[mt][nt], ahi[mt], blo[ng][sel], blo[ng][sel + 2]);
                    mma16816(acc[mt][nt], alo[mt], bhi[ng][sel], bhi[ng][sel + 2]);
                }
        }
        __syncthreads();
    }

    // ---- epilogue ----
    const int qr = lane >> 2, qc = (lane & 3) << 1;
#pragma unroll
    for (int mt = 0; mt < 2; mt++) {
#pragma unroll
        for (int nt = 0; nt < 8; nt++) {
#pragma unroll
            for (int half = 0; half < 2; half++) {
                int row = m0 + wm + mt * 16 + qr + (half << 3);
                int col = n0 + wn + nt * 8 + qc;
                float v0 = (acc[mt][nt][half * 2 + 0] + bias[col])     * scale;
                float v1 = (acc[mt][nt][half * 2 + 1] + bias[col + 1]) * scale;
                if (mode == 2) {
                    *(float2*)&outF[(size_t)row * EDIM + col] = make_float2(v0, v1);
                } else {
                    int pos = row >> 2;              // B = 4
                    int b = row & 3;
                    int h = col >> 6, d = col & 63;
                    size_t o = ((size_t)(b * HDIM + h) * npos + pos) * DHD + d;
                    if (mode == 1) {
                        v0 = fast_sigmoid(v0); v1 = fast_sigmoid(v1);
                        *(float2*)&outF[o] = make_float2(v0, v1);
                    } else {
                        __nv_bfloat16 h0 = __float2bfloat16(v0), h1 = __float2bfloat16(v1);
                        __nv_bfloat16 l0 = __float2bfloat16(v0 - __bfloat162float(h0));
                        __nv_bfloat16 l1 = __float2bfloat16(v1 - __bfloat162float(h1));
                        *(__nv_bfloat162*)&outHi[o] = __nv_bfloat162(h0, h1);
                        *(__nv_bfloat162*)&outLo[o] = __nv_bfloat162(l0, l1);
                    }
                }
            }
        }
    }
#undef LOAD_STAGE
}

// ---------------- per-row stats from bf16 hi/lo ----------------
__global__ void k_qstats(const __nv_bfloat16* __restrict__ qhi,
                         const __nv_bfloat16* __restrict__ qlo, float* __restrict__ ll)
{
    int gw = (blockIdx.x * blockDim.x + threadIdx.x) >> 5;
    int lane = threadIdx.x & 31;
    if (gw >= BH*LQ) return;
    const __nv_bfloat162* h = (const __nv_bfloat162*)(qhi + (size_t)gw * DHD);
    const __nv_bfloat162* l = (const __nv_bfloat162*)(qlo + (size_t)gw * DHD);
    __nv_bfloat162 hv = h[lane], lv = l[lane];
    float x0 = __bfloat162float(hv.x) + __bfloat162float(lv.x);
    float x1 = __bfloat162float(hv.y) + __bfloat162float(lv.y);
    float s = x0*x0 + x1*x1;
#pragma unroll
    for (int o = 16; o; o >>= 1) s += __shfl_xor_sync(0xffffffffu, s, o);
    if (!lane) ll[gw] = s;
}

__global__ void k_kstats(const __nv_bfloat16* __restrict__ k1hi, const __nv_bfloat16* __restrict__ k1lo,
                         const __nv_bfloat16* __restrict__ k2hi, const __nv_bfloat16* __restrict__ k2lo,
                         float* __restrict__ vv, float* __restrict__ aa, float* __restrict__ va)
{
    int gw = (blockIdx.x * blockDim.x + threadIdx.x) >> 5;
    int lane = threadIdx.x & 31;
    if (gw >= BH*SK) return;
    const __nv_bfloat162* ah = (const __nv_bfloat162*)(k1hi + (size_t)gw * DHD);
    const __nv_bfloat162* al = (const __nv_bfloat162*)(k1lo + (size_t)gw * DHD);
    const __nv_bfloat162* bh = (const __nv_bfloat162*)(k2hi + (size_t)gw * DHD);
    const __nv_bfloat162* bl = (const __nv_bfloat162*)(k2lo + (size_t)gw * DHD);
    __nv_bfloat162 a2 = ah[lane], a2l = al[lane], b2 = bh[lane], b2l = bl[lane];
    float a0 = __bfloat162float(a2.x) + __bfloat162float(a2l.x);
    float a1 = __bfloat162float(a2.y) + __bfloat162float(a2l.y);
    float b0 = __bfloat162float(b2.x) + __bfloat162float(b2l.x);
    float b1 = __bfloat162float(b2.y) + __bfloat162float(b2l.y);
    float svv = a0*a0 + a1*a1, saa = b0*b0 + b1*b1, sva = a0*b0 + a1*b1;
#pragma unroll
    for (int o = 16; o; o >>= 1) {
        svv += __shfl_xor_sync(0xffffffffu, svv, o);
        saa += __shfl_xor_sync(0xffffffffu, saa, o);
        sva += __shfl_xor_sync(0xffffffffu, sva, o);
    }
    if (!lane) { vv[gw] = svv; aa[gw] = saa; va[gw] = sva; }
}

// ================== logits via bf16x3 MMA + poly sqrt ==================
// CTA tile 64(l) x 128(s), warps 2x4 (each 32x32). K = DH = 64 single-shot.
#define LG_PAD 72
#define LG_QT (64 * LG_PAD * 2)     // 9216
#define LG_KT (128 * LG_PAD * 2)    // 18432
#define LG_SMEM (2*LG_QT + 4*LG_KT) // 92160

__global__ void __launch_bounds__(256, 1)
k_logits_mma(const __nv_bfloat16* __restrict__ qhi, const __nv_bfloat16* __restrict__ qlo,
             const __nv_bfloat16* __restrict__ k1hi, const __nv_bfloat16* __restrict__ k1lo,
             const __nv_bfloat16* __restrict__ k2hi, const __nv_bfloat16* __restrict__ k2lo,
             const float* __restrict__ ll, const float* __restrict__ vv,
             const float* __restrict__ aa, const float* __restrict__ va,
             float* __restrict__ A)
{
    extern __shared__ char smem[];
    const uint32_t sb = smem_to_u32(smem);
    const int tid = threadIdx.x, wid = tid >> 5, lane = tid & 31;
    const int bh = blockIdx.z, l0 = blockIdx.y << 6, s0 = blockIdx.x << 7;
    const uint32_t oQh = 0, oQl = LG_QT, oK1h = 2*LG_QT, oK1l = 2*LG_QT + LG_KT,
                   oK2h = 2*LG_QT + 2*LG_KT, oK2l = 2*LG_QT + 3*LG_KT;

    {   // Q tiles: 64 rows x 8 chunks
        const __nv_bfloat16* qh = qhi + ((size_t)(bh * LQ + l0) << 6);
        const __nv_bfloat16* ql = qlo + ((size_t)(bh * LQ + l0) << 6);
#pragma unroll
        for (int i = tid; i < 512; i += 256) {
            int r = i >> 3, c = i & 7;
            uint32_t d = (uint32_t)(r * (LG_PAD*2) + c * 16);
            *(uint4*)(smem + oQh + d) = *(const uint4*)(qh + (r << 6) + (c << 3));
            *(uint4*)(smem + oQl + d) = *(const uint4*)(ql + (r << 6) + (c << 3));
        }
        const __nv_bfloat16* p1h = k1hi + ((size_t)(bh * SK + s0) << 6);
        const __nv_bfloat16* p1l = k1lo + ((size_t)(bh * SK + s0) << 6);
        const __nv_bfloat16* p2h = k2hi + ((size_t)(bh * SK + s0) << 6);
        const __nv_bfloat16* p2l = k2lo + ((size_t)(bh * SK + s0) << 6);
#pragma unroll
        for (int i = tid; i < 1024; i += 256) {
            int r = i >> 3, c = i & 7;
            uint32_t d = (uint32_t)(r * (LG_PAD*2) + c * 16);
            *(uint4*)(smem + oK1h + d) = *(const uint4*)(p1h + (r << 6) + (c << 3));
            *(uint4*)(smem + oK1l + d) = *(const uint4*)(p1l + (r << 6) + (c << 3));
            *(uint4*)(smem + oK2h + d) = *(const uint4*)(p2h + (r << 6) + (c << 3));
            *(uint4*)(smem + oK2l + d) = *(const uint4*)(p2l + (r << 6) + (c << 3));
        }
    }
    __syncthreads();

    const int wm = (wid & 1) << 5, wn = (wid >> 1) << 5;
    float lv[2][4][4] = {}, la[2][4][4] = {};
#pragma unroll
    for (int kk = 0; kk < 4; kk++) {
        const uint32_t coff = (uint32_t)(kk * 16 + ((lane >> 4) << 3)) * 2u;
        uint32_t af[2][4], alf[2][4];
#pragma unroll
        for (int mt = 0; mt < 2; mt++) {
            uint32_t ra = (uint32_t)((wm + mt * 16 + (lane & 15)) * LG_PAD) * 2u + coff;
            ldm_x4(af[mt],  sb + oQh + ra);
            ldm_x4(alf[mt], sb + oQl + ra);
        }
        uint32_t b1h[2][4], b1l[2][4], b2h[2][4], b2l[2][4];
#pragma unroll
        for (int ng = 0; ng < 2; ng++) {
            uint32_t rb = (uint32_t)((wn + ng * 16 + (lane & 15)) * LG_PAD) * 2u + coff;
            ldm_x4(b1h[ng], sb + oK1h + rb);
            ldm_x4(b1l[ng], sb + oK1l + rb);
            ldm_x4(b2h[ng], sb + oK2h + rb);
            ldm_x4(b2l[ng], sb + oK2l + rb);
        }
#pragma unroll
        for (int mt = 0; mt < 2; mt++)
#pragma unroll
            for (int nt = 0; nt < 4; nt++) {
                const int ng = nt >> 1, sel = nt & 1;
                mma16816(lv[mt][nt], af[mt],  b1h[ng][sel], b1h[ng][sel + 2]);
                mma16816(lv[mt][nt], af[mt],  b1l[ng][sel], b1l[ng][sel + 2]);
                mma16816(lv[mt][nt], alf[mt], b1h[ng][sel], b1h[ng][sel + 2]);
                mma16816(la[mt][nt], af[mt],  b2h[ng][sel], b2h[ng][sel + 2]);
                mma16816(la[mt][nt], af[mt],  b2l[ng][sel], b2l[ng][sel + 2]);
                mma16816(la[mt][nt], alf[mt], b2h[ng][sel], b2h[ng][sel + 2]);
            }
    }

    // epilogue: det + poly sqrt, write fp32 logits
    const int qr = lane >> 2, qc = (lane & 3) << 1;
    float vvc[8], aac[8], vac[8];
#pragma unroll
    for (int nt = 0; nt < 4; nt++)
#pragma unroll
        for (int j = 0; j < 2; j++) {
            int c = bh * SK + s0 + wn + nt * 8 + qc + j;
            vvc[nt*2+j] = __ldg(&vv[c]); aac[nt*2+j] = __ldg(&aa[c]); vac[nt*2+j] = __ldg(&va[c]);
        }
#pragma unroll
    for (int mt = 0; mt < 2; mt++)
#pragma unroll
        for (int half = 0; half < 2; half++) {
            int l = l0 + wm + mt * 16 + qr + (half << 3);
            float llr = __ldg(&ll[bh * LQ + l]);
            float* rowp = A + (((size_t)(bh * LQ + l)) << 10);
#pragma unroll
            for (int nt = 0; nt < 4; nt++) {
                float r2[2];
#pragma unroll
                for (int j = 0; j < 2; j++) {
                    float LV = lv[mt][nt][half * 2 + j];
                    float LA = la[mt][nt][half * 2 + j];
                    int ci = nt * 2 + j;
                    float det = llr * (vvc[ci] * aac[ci] - vac[ci] * vac[ci])
                              - LV * (LV * aac[ci] - LA * vac[ci])
                              + LA * (LV * vac[ci] - LA * vvc[ci]);
                    det = fmaxf(det, 1e-8f);
                    r2[j] = LV + LA - 1.5f * fast_sqrt(det);
                }
                *(float2*)&rowp[s0 + wn + nt * 8 + qc] = make_float2(r2[0], r2[1]);
            }
        }
}

// ---------------- softmax: fp32 logits -> bf16 hi/lo probs (poly exp) ----------------
__global__ void k_softmax(const float* __restrict__ A, __nv_bfloat16* __restrict__ Phi,
                          __nv_bfloat16* __restrict__ Plo)
{
    const int row = blockIdx.x;
    const float* p = A + (size_t)row * SK;
    const int t = threadIdx.x;                 // 256 threads, 4 consecutive elems
    float4 x = *(const float4*)(p + t * 4);
    float m = fmaxf(fmaxf(x.x, x.y), fmaxf(x.z, x.w));
    __shared__ float sred[8];
    __shared__ float sinv;
#pragma unroll
    for (int o = 16; o; o >>= 1) m = fmaxf(m, __shfl_xor_sync(0xffffffffu, m, o));
    if ((t & 31) == 0) sred[t >> 5] = m;
    __syncthreads();
    if (t < 8) {
        float v = sred[t];
#pragma unroll
        for (int o = 4; o; o >>= 1) v = fmaxf(v, __shfl_xor_sync(0xffu, v, o));
        sred[t] = v;
    }
    __syncthreads();
    m = sred[0];
    float e0 = fast_exp(x.x - m), e1 = fast_exp(x.y - m);
    float e2 = fast_exp(x.z - m), e3 = fast_exp(x.w - m);
    float s = (e0 + e1) + (e2 + e3);
#pragma unroll
    for (int o = 16; o; o >>= 1) s += __shfl_xor_sync(0xffffffffu, s, o);
    __shared__ float sred2[8];
    if ((t & 31) == 0) sred2[t >> 5] = s;
    __syncthreads();
    if (t < 8) {
        float v = sred2[t];
#pragma unroll
        for (int o = 4; o; o >>= 1) v += __shfl_xor_sync(0xffu, v, o);
        if (t == 0) sinv = 1.0f / v;          // one MUFU per row: negligible
    }
    __syncthreads();
    float inv = sinv;
    float v0 = e0 * inv, v1 = e1 * inv, v2 = e2 * inv, v3 = e3 * inv;
    __nv_bfloat16 h0 = __float2bfloat16(v0), h1 = __float2bfloat16(v1);
    __nv_bfloat16 h2 = __float2bfloat16(v2), h3 = __float2bfloat16(v3);
    __nv_bfloat16 l0 = __float2bfloat16(v0 - __bfloat162float(h0));
    __nv_bfloat16 l1 = __float2bfloat16(v1 - __bfloat162float(h1));
    __nv_bfloat16 l2 = __float2bfloat16(v2 - __bfloat162float(h2));
    __nv_bfloat16 l3 = __float2bfloat16(v3 - __bfloat162float(h3));
    size_t o = (size_t)row * SK + t * 4;
    ((__nv_bfloat162*)(Phi + o))[0] = __nv_bfloat162(h0, h1);
    ((__nv_bfloat162*)(Phi + o))[1] = __nv_bfloat162(h2, h3);
    ((__nv_bfloat162*)(Plo + o))[0] = __nv_bfloat162(l0, l1);
    ((__nv_bfloat162*)(Plo + o))[1] = __nv_bfloat162(l2, l3);
}

// ---------------- head-average of probs (hi+lo reconstruct) ----------------
__global__ void k_avg(const __nv_bfloat16* __restrict__ Phi, const __nv_bfloat16* __restrict__ Plo,
                      float* __restrict__ avg)
{
    size_t idx = (size_t)blockIdx.x * 256 + threadIdx.x;
    if (idx >= (size_t)BDIM * LQ * SK) return;
    int s = idx & (SK - 1);
    int l = (idx >> 10) & (LQ - 1);
    int b = (int)(idx >> 19);
    size_t base = ((size_t)b * HDIM) * LQ * SK + (size_t)l * SK + s;
    float acc = 0.f;
#pragma unroll
    for (int h = 0; h < HDIM; h++) {
        size_t o = base + (size_t)h * LQ * SK;
        acc += __bfloat162float(Phi[o]) + __bfloat162float(Plo[o]);
    }
    avg[idx] = acc * (1.f / HDIM);
}

// ================== attn @ V (bf16x3 MMA) + gate + split -> cb hi/lo ==================
// CTA tile 64(l) x 64(d) per bh, K = S = 1024 in 16 chunks of 64.
// warps 2x4: each 32(l) x 16(d).
#define AV_PAD 72
#define AV_T (64 * AV_PAD * 2)        // 9216 per 64-row tile
#define AV_STAGE (6 * AV_T)           // athi, atlo, v1h, v1l, v2h, v2l
#define AV_SMEM (2 * AV_STAGE)        // 110592

__global__ void __launch_bounds__(256, 1)
k_av_mma(const __nv_bfloat16* __restrict__ athi, const __nv_bfloat16* __restrict__ atlo,
         const __nv_bfloat16* __restrict__ v1hi, const __nv_bfloat16* __restrict__ v1lo,
         const __nv_bfloat16* __restrict__ v2hi, const __nv_bfloat16* __restrict__ v2lo,
         const float* __restrict__ G1, const float* __restrict__ G2,
         __nv_bfloat16* __restrict__ cbhi, __nv_bfloat16* __restrict__ cblo)
{
    extern __shared__ char smem[];
    const uint32_t sb = smem_to_u32(smem);
    const int tid = threadIdx.x, wid = tid >> 5, lane = tid & 31;
    const int bh = blockIdx.y, l0 = blockIdx.x << 6;
    const int wm = (wid & 1) << 5, wn = (wid >> 1) << 4;

    float acc1[2][2][4] = {}, acc2[2][2][4] = {};

#define AV_LOAD(stg, s0k) do { \
    _Pragma("unroll") \
    for (int i = 0; i < 12; i++) { \
        int id = (i << 8) + tid; \
        int a = id >> 9; \
        int rr = (id >> 3) & 63; \
        int c = id & 7; \
        const __nv_bfloat16* g; \
        if (a < 2) g = (a ? atlo : athi) + (((size_t)(bh * LQ + l0 + rr)) << 10) + (s0k) + (c << 3); \
        else { \
            const __nv_bfloat16* vb = (a == 2) ? v1hi : (a == 3) ? v1lo : (a == 4) ? v2hi : v2lo; \
            g = vb + (((size_t)(bh * SK + (s0k) + rr)) << 6) + (c << 3); \
        } \
        uint32_t sa = sb + (uint32_t)(stg) * AV_STAGE + (uint32_t)a * AV_T + (uint32_t)(rr * (AV_PAD*2) + c * 16); \
        CP_ASYNC16(sa, g); \
    } \
    CP_COMMIT(); \
} while (0)

    AV_LOAD(0, 0);

    for (int ch = 0; ch < 16; ch++) {
        const int stg = ch & 1;
        if (ch + 1 < 16) { AV_LOAD(stg ^ 1, (ch + 1) << 6); CP_WAIT(1); }
        else             { CP_WAIT(0); }
        __syncthreads();

        const uint32_t st = sb + (uint32_t)stg * AV_STAGE;
#pragma unroll
        for (int kk = 0; kk < 4; kk++) {
            const uint32_t coff = (uint32_t)(kk * 16 + ((lane >> 4) << 3)) * 2u;
            uint32_t af[2][4], alf[2][4];
#pragma unroll
            for (int mt = 0; mt < 2; mt++) {
                uint32_t ra = (uint32_t)((wm + mt * 16 + (lane & 15)) * AV_PAD) * 2u + coff;
                ldm_x4(af[mt],  st + ra);                 // attn hi
                ldm_x4(alf[mt], st + AV_T + ra);          // attn lo
            }
            // V frags via ldmatrix.trans (V stored k-major [s][d])
            uint32_t bv1h[4], bv1l[4], bv2h[4], bv2l[4];
            {
                uint32_t rb = (uint32_t)((kk * 16 + (lane & 15)) * AV_PAD + wn + ((lane >> 4) << 3)) * 2u;
                ldm_x4_t(bv1h, st + 2 * AV_T + rb);
                ldm_x4_t(bv1l, st + 3 * AV_T + rb);
                ldm_x4_t(bv2h, st + 4 * AV_T + rb);
                ldm_x4_t(bv2l, st + 5 * AV_T + rb);
            }
#pragma unroll
            for (int mt = 0; mt < 2; mt++)
#pragma unroll
                for (int nt = 0; nt < 2; nt++) {
                    // trans frag pairing: n-half nt -> (regs[nt*2], regs[nt*2+1])
                    mma16816(acc1[mt][nt], af[mt],  bv1h[nt*2], bv1h[nt*2+1]);
                    mma16816(acc1[mt][nt], af[mt],  bv1l[nt*2], bv1l[nt*2+1]);
                    mma16816(acc1[mt][nt], alf[mt], bv1h[nt*2], bv1h[nt*2+1]);
                    mma16816(acc2[mt][nt], af[mt],  bv2h[nt*2], bv2h[nt*2+1]);
                    mma16816(acc2[mt][nt], af[mt],  bv2l[nt*2], bv2l[nt*2+1]);
                    mma16816(acc2[mt][nt], alf[mt], bv2h[nt*2], bv2h[nt*2+1]);
                }
        }
        __syncthreads();
    }

    // ---- epilogue: gate + combine + bf16 split -> cb ----
    const int qr = lane >> 2, qc = (lane & 3) << 1;
    const int b_ = bh >> 4, h_ = bh & 15;
#pragma unroll
    for (int mt = 0; mt < 2; mt++)
#pragma unroll
        for (int half = 0; half < 2; half++) {
            int l = l0 + wm + mt * 16 + qr + (half << 3);
            const float* g1r = G1 + ((size_t)(bh * LQ + l)) * DHD;
            const float* g2r = G2 + ((size_t)(bh * LQ + l)) * DHD;
            size_t rowo = ((size_t)(l * BDIM + b_)) << 10;
#pragma unroll
            for (int nt = 0; nt < 2; nt++) {
                int d = wn + nt * 8 + qc;
                float2 g1 = *(const float2*)&g1r[d];
                float2 g2 = *(const float2*)&g2r[d];
                float c0 = (acc1[mt][nt][half*2+0] * g1.x + acc2[mt][nt][half*2+0] * g2.x) * 0.5f;
                float c1 = (acc1[mt][nt][half*2+1] * g1.y + acc2[mt][nt][half*2+1] * g2.y) * 0.5f;
                __nv_bfloat16 h0 = __float2bfloat16(c0), h1 = __float2bfloat16(c1);
                __nv_bfloat16 l0b = __float2bfloat16(c0 - __bfloat162float(h0));
                __nv_bfloat16 l1b = __float2bfloat16(c1 - __bfloat162float(h1));
                size_t o = rowo + h_ * DHD + d;
                *(__nv_bfloat162*)&cbhi[o] = __nv_bfloat162(h0, h1);
                *(__nv_bfloat162*)&cblo[o] = __nv_bfloat162(l0b, l1b);
            }
        }
#undef AV_LOAD
}

// ---------------- launch ----------------
extern "C" void kernel_launch(void* const* d_in, const int* in_sizes, int n_in,
                              void* d_out, int out_size)
{
    const float* query = (const float*)d_in[0];
    const float* mod1  = (const float*)d_in[1];
    const float* mod2  = (const float*)d_in[2];
    WPtrs wp;
    const float* bi[8];
    for (int i = 0; i < 8; i++) {           // q k1 k2 v1 v2 g1 g2 o
        wp.p[i] = (const float*)d_in[3 + 2*i];
        bi[i]   = (const float*)d_in[4 + 2*i];
    }
    float* out = (float*)d_out;
    float* avg_out = out + (size_t)LQ * BDIM * EDIM;

    float *G1h, *G2h, *ll, *vv, *aa, *va, *Attn;
    cudaGetSymbolAddress((void**)&G1h, g_G1h);
    cudaGetSymbolAddress((void**)&G2h, g_G2h);
    cudaGetSymbolAddress((void**)&ll,  g_ll);
    cudaGetSymbolAddress((void**)&vv,  g_vv);
    cudaGetSymbolAddress((void**)&aa,  g_aa);
    cudaGetSymbolAddress((void**)&va,  g_va);
    cudaGetSymbolAddress((void**)&Attn, g_Attn);

    __nv_bfloat16 *qhi,*qlo,*k1hi,*k1lo,*k2hi,*k2lo,*v1hi,*v1lo,*v2hi,*v2lo,*athi,*atlo;
    __nv_bfloat16 *xq_hi,*xq_lo,*m1_hi,*m1_lo,*m2_hi,*m2_lo,*cb_hi,*cb_lo,*wt_hi,*wt_lo;
    cudaGetSymbolAddress((void**)&qhi,  g_q_hi);  cudaGetSymbolAddress((void**)&qlo,  g_q_lo);
    cudaGetSymbolAddress((void**)&k1hi, g_k1_hi); cudaGetSymbolAddress((void**)&k1lo, g_k1_lo);
    cudaGetSymbolAddress((void**)&k2hi, g_k2_hi); cudaGetSymbolAddress((void**)&k2lo, g_k2_lo);
    cudaGetSymbolAddress((void**)&v1hi, g_v1_hi); cudaGetSymbolAddress((void**)&v1lo, g_v1_lo);
    cudaGetSymbolAddress((void**)&v2hi, g_v2_hi); cudaGetSymbolAddress((void**)&v2lo, g_v2_lo);
    cudaGetSymbolAddress((void**)&athi, g_at_hi); cudaGetSymbolAddress((void**)&atlo, g_at_lo);
    cudaGetSymbolAddress((void**)&xq_hi, g_xq_hi); cudaGetSymbolAddress((void**)&xq_lo, g_xq_lo);
    cudaGetSymbolAddress((void**)&m1_hi, g_m1_hi); cudaGetSymbolAddress((void**)&m1_lo, g_m1_lo);
    cudaGetSymbolAddress((void**)&m2_hi, g_m2_hi); cudaGetSymbolAddress((void**)&m2_lo, g_m2_lo);
    cudaGetSymbolAddress((void**)&cb_hi, g_cb_hi); cudaGetSymbolAddress((void**)&cb_lo, g_cb_lo);
    cudaGetSymbolAddress((void**)&wt_hi, g_wt_hi); cudaGetSymbolAddress((void**)&wt_lo, g_wt_lo);

    cudaFuncSetAttribute(gemm_mma,     cudaFuncAttributeMaxDynamicSharedMemorySize, GM_SMEM);
    cudaFuncSetAttribute(k_logits_mma, cudaFuncAttributeMaxDynamicSharedMemorySize, LG_SMEM);
    cudaFuncSetAttribute(k_av_mma,     cudaFuncAttributeMaxDynamicSharedMemorySize, AV_SMEM);

    // 0: fused input split
    k_split_all<<<10240, 256>>>(query, mod1, mod2, xq_hi, xq_lo, m1_hi, m1_lo, m2_hi, m2_lo);
    // 1: fused weight transpose+split
    k_wsplit_all<<<dim3(32, 32, 8), dim3(32, 8)>>>(wp, wt_hi, wt_lo);

    // 2-8: projections
    dim3 gq(8, 16);   // 2048 rows
    dim3 gk(8, 32);   // 4096 rows
    size_t WSZ = (size_t)1024*1024;
    gemm_mma<<<gq, 256, GM_SMEM>>>(xq_hi, xq_lo, wt_hi+0*WSZ, wt_lo+0*WSZ, bi[0], nullptr, qhi,  qlo,  LQ, 0.125f, 0);
    gemm_mma<<<gk, 256, GM_SMEM>>>(m1_hi, m1_lo, wt_hi+1*WSZ, wt_lo+1*WSZ, bi[1], nullptr, k1hi, k1lo, SK, 1.f,    0);
    gemm_mma<<<gk, 256, GM_SMEM>>>(m2_hi, m2_lo, wt_hi+2*WSZ, wt_lo+2*WSZ, bi[2], nullptr, k2hi, k2lo, SK, 1.f,    0);
    gemm_mma<<<gk, 256, GM_SMEM>>>(m1_hi, m1_lo, wt_hi+3*WSZ, wt_lo+3*WSZ, bi[3], nullptr, v1hi, v1lo, SK, 1.f,    0);
    gemm_mma<<<gk, 256, GM_SMEM>>>(m2_hi, m2_lo, wt_hi+4*WSZ, wt_lo+4*WSZ, bi[4], nullptr, v2hi, v2lo, SK, 1.f,    0);
    gemm_mma<<<gq, 256, GM_SMEM>>>(xq_hi, xq_lo, wt_hi+5*WSZ, wt_lo+5*WSZ, bi[5], G1h, nullptr, nullptr, LQ, 1.f, 1);
    gemm_mma<<<gq, 256, GM_SMEM>>>(xq_hi, xq_lo, wt_hi+6*WSZ, wt_lo+6*WSZ, bi[6], G2h, nullptr, nullptr, LQ, 1.f, 1);

    // 9-10: stats
    k_qstats<<<(BH*LQ*32 + 255)/256, 256>>>(qhi, qlo, ll);
    k_kstats<<<(BH*SK*32 + 255)/256, 256>>>(k1hi, k1lo, k2hi, k2lo, vv, aa, va);

    // 11: logits (MMA + poly sqrt)
    k_logits_mma<<<dim3(SK/128, LQ/64, BH), 256, LG_SMEM>>>(
        qhi, qlo, k1hi, k1lo, k2hi, k2lo, ll, vv, aa, va, Attn);
    // 12: softmax (poly exp) -> bf16 hi/lo probs
    k_softmax<<<BH*LQ, 256>>>(Attn, athi, atlo);
    // 13: head-average
    if ((size_t)out_size >= 2ULL * LQ * BDIM * EDIM)
        k_avg<<<(BDIM*LQ*SK + 255)/256, 256>>>(athi, atlo, avg_out);
    // 14: attn @ V + gating -> cb hi/lo
    k_av_mma<<<dim3(LQ/64, BH), 256, AV_SMEM>>>(athi, atlo, v1hi, v1lo, v2hi, v2lo,
                                                G1h, G2h, cb_hi, cb_lo);
    // 15: output projection
    gemm_mma<<<gq, 256, GM_SMEM>>>(cb_hi, cb_lo, wt_hi+7*WSZ, wt_lo+7*WSZ, bi[7], out,
                                   nullptr, nullptr, LQ, 1.f, 2);
}

// round 5
// speedup vs baseline: 2.7898x; 1.0470x over previous
#include <cuda_runtime.h>
#include <cuda_bf16.h>
#include <math.h>
#include <stdint.h>

#define EDIM 1024
#define BDIM 4
#define HDIM 16
#define DHD 64
#define LQ 512
#define SK 1024
#define BH 64   // BDIM*HDIM

// ======================= helpers =======================
__device__ __forceinline__ uint32_t smem_to_u32(const void* smem_ptr) {
    uint32_t addr;
    asm("{ .reg .u64 tmp; cvta.to.shared.u64 tmp, %1; cvt.u32.u64 %0, tmp; }"
        : "=r"(addr) : "l"(smem_ptr));
    return addr;
}
__device__ __forceinline__ void ldm_x4(uint32_t* r, uint32_t addr) {
    asm volatile("ldmatrix.sync.aligned.m8n8.x4.shared.b16 {%0,%1,%2,%3}, [%4];"
        : "=r"(r[0]), "=r"(r[1]), "=r"(r[2]), "=r"(r[3]) : "r"(addr));
}
__device__ __forceinline__ void ldm_x4_t(uint32_t* r, uint32_t addr) {
    asm volatile("ldmatrix.sync.aligned.m8n8.x4.trans.shared.b16 {%0,%1,%2,%3}, [%4];"
        : "=r"(r[0]), "=r"(r[1]), "=r"(r[2]), "=r"(r[3]) : "r"(addr));
}
__device__ __forceinline__ void mma16816(float* d, const uint32_t* a, uint32_t b0, uint32_t b1) {
    asm volatile("mma.sync.aligned.m16n8k16.row.col.f32.bf16.bf16.f32 "
        "{%0,%1,%2,%3}, {%4,%5,%6,%7}, {%8,%9}, {%0,%1,%2,%3};"
        : "+f"(d[0]), "+f"(d[1]), "+f"(d[2]), "+f"(d[3])
        : "r"(a[0]), "r"(a[1]), "r"(a[2]), "r"(a[3]), "r"(b0), "r"(b1));
}
#define CP_ASYNC16(saddr, gptr) \
    asm volatile("cp.async.cg.shared.global [%0], [%1], 16;" :: "r"(saddr), "l"(gptr))
#define CP_COMMIT()  asm volatile("cp.async.commit_group;" ::: "memory")
#define CP_WAIT(N)   asm volatile("cp.async.wait_group %0;" :: "n"(N) : "memory")

// ---- MUFU-free math (FFMA/ALU only) ----
__device__ __forceinline__ float fast_sqrt(float x) {
    float r = __int_as_float(0x5f3759df - (__float_as_int(x) >> 1));
    r = r * fmaf(-0.5f * x * r, r, 1.5f);
    r = r * fmaf(-0.5f * x * r, r, 1.5f);
    r = r * fmaf(-0.5f * x * r, r, 1.5f);
    return x * r;
}
__device__ __forceinline__ float fast_exp(float x) {
    float y = x * 1.44269504f;
    y = fmaxf(fminf(y, 126.0f), -125.0f);
    float t = y + 12582912.f;
    int n = __float_as_int(t) - 0x4B400000;
    float f = y - (t - 12582912.f);
    float p = 1.33335581e-3f;
    p = fmaf(p, f, 9.61812910e-3f);
    p = fmaf(p, f, 5.55041086e-2f);
    p = fmaf(p, f, 2.40226507e-1f);
    p = fmaf(p, f, 6.93147181e-1f);
    p = fmaf(p, f, 1.0f);
    return __int_as_float(__float_as_int(p) + (n << 23));
}
__device__ __forceinline__ float fast_rcp(float x) {
    float r = __int_as_float(0x7EF311C3 - __float_as_int(x));
    r = r * (2.0f - x * r);
    r = r * (2.0f - x * r);
    r = r * (2.0f - x * r);
    return r;
}
__device__ __forceinline__ float fast_sigmoid(float x) {
    return fast_rcp(1.0f + fast_exp(-x));
}

// ---------------- scratch ----------------
__device__ float g_G1h[BH*LQ*DHD];
__device__ float g_G2h[BH*LQ*DHD];
__device__ float g_ll [BH*LQ];
__device__ float g_vv [BH*SK];
__device__ float g_aa [BH*SK];
__device__ float g_va [BH*SK];
__device__ float g_Attn[BH*LQ*SK];

__device__ __align__(16) __nv_bfloat16 g_q_hi [BH*LQ*DHD];
__device__ __align__(16) __nv_bfloat16 g_q_lo [BH*LQ*DHD];
__device__ __align__(16) __nv_bfloat16 g_k1_hi[BH*SK*DHD];
__device__ __align__(16) __nv_bfloat16 g_k1_lo[BH*SK*DHD];
__device__ __align__(16) __nv_bfloat16 g_k2_hi[BH*SK*DHD];
__device__ __align__(16) __nv_bfloat16 g_k2_lo[BH*SK*DHD];
__device__ __align__(16) __nv_bfloat16 g_v1_hi[BH*SK*DHD];
__device__ __align__(16) __nv_bfloat16 g_v1_lo[BH*SK*DHD];
__device__ __align__(16) __nv_bfloat16 g_v2_hi[BH*SK*DHD];
__device__ __align__(16) __nv_bfloat16 g_v2_lo[BH*SK*DHD];
__device__ __align__(16) __nv_bfloat16 g_at_hi[BH*LQ*SK];
__device__ __align__(16) __nv_bfloat16 g_at_lo[BH*LQ*SK];
__device__ __align__(16) __nv_bfloat16 g_xq_hi[2048*1024];
__device__ __align__(16) __nv_bfloat16 g_xq_lo[2048*1024];
__device__ __align__(16) __nv_bfloat16 g_m1_hi[4096*1024];
__device__ __align__(16) __nv_bfloat16 g_m1_lo[4096*1024];
__device__ __align__(16) __nv_bfloat16 g_m2_hi[4096*1024];
__device__ __align__(16) __nv_bfloat16 g_m2_lo[4096*1024];
__device__ __align__(16) __nv_bfloat16 g_cb_hi[2048*1024];
__device__ __align__(16) __nv_bfloat16 g_cb_lo[2048*1024];
__device__ __align__(16) __nv_bfloat16 g_wt_hi[8*1024*1024];
__device__ __align__(16) __nv_bfloat16 g_wt_lo[8*1024*1024];

// ---------------- fused input split ----------------
__global__ void k_split_all(const float* __restrict__ q, const float* __restrict__ m1,
                            const float* __restrict__ m2,
                            __nv_bfloat16* __restrict__ qhi, __nv_bfloat16* __restrict__ qlo,
                            __nv_bfloat16* __restrict__ m1hi, __nv_bfloat16* __restrict__ m1lo,
                            __nv_bfloat16* __restrict__ m2hi, __nv_bfloat16* __restrict__ m2lo)
{
    int i = blockIdx.x * 256 + threadIdx.x;
    const float* src; __nv_bfloat16 *hi, *lo; int off;
    if (i < 512*1024)        { src = q;  hi = qhi;  lo = qlo;  off = i; }
    else if (i < 1536*1024)  { src = m1; hi = m1hi; lo = m1lo; off = i - 512*1024; }
    else                     { src = m2; hi = m2hi; lo = m2lo; off = i - 1536*1024; }
    float4 v = ((const float4*)src)[off];
    __nv_bfloat16 h0 = __float2bfloat16(v.x), h1 = __float2bfloat16(v.y);
    __nv_bfloat16 h2 = __float2bfloat16(v.z), h3 = __float2bfloat16(v.w);
    __nv_bfloat16 l0 = __float2bfloat16(v.x - __bfloat162float(h0));
    __nv_bfloat16 l1 = __float2bfloat16(v.y - __bfloat162float(h1));
    __nv_bfloat16 l2 = __float2bfloat16(v.z - __bfloat162float(h2));
    __nv_bfloat16 l3 = __float2bfloat16(v.w - __bfloat162float(h3));
    __nv_bfloat162* hp = (__nv_bfloat162*)(hi + (size_t)off * 4);
    __nv_bfloat162* lp = (__nv_bfloat162*)(lo + (size_t)off * 4);
    hp[0] = __nv_bfloat162(h0, h1); hp[1] = __nv_bfloat162(h2, h3);
    lp[0] = __nv_bfloat162(l0, l1); lp[1] = __nv_bfloat162(l2, l3);
}

// ---------------- weight transpose + split ----------------
struct WPtrs { const float* p[8]; };
__global__ void k_wsplit_all(WPtrs wp, __nv_bfloat16* __restrict__ ThiAll,
                             __nv_bfloat16* __restrict__ TloAll)
{
    __shared__ float t[32][33];
    const int wi = blockIdx.z;
    const float* W = wp.p[wi];
    __nv_bfloat16* Thi = ThiAll + (size_t)wi * 1024 * 1024;
    __nv_bfloat16* Tlo = TloAll + (size_t)wi * 1024 * 1024;
    const int bx = blockIdx.x << 5;
    const int by = blockIdx.y << 5;
    const int x = threadIdx.x, y = threadIdx.y;
#pragma unroll
    for (int i = 0; i < 32; i += 8)
        t[y + i][x] = W[(size_t)(by + y + i) * EDIM + bx + x];
    __syncthreads();
#pragma unroll
    for (int i = 0; i < 32; i += 8) {
        float v = t[x][y + i];
        __nv_bfloat16 h = __float2bfloat16(v);
        __nv_bfloat16 l = __float2bfloat16(v - __bfloat162float(h));
        size_t o = (size_t)(bx + y + i) * EDIM + by + x;
        Thi[o] = h; Tlo[o] = l;
    }
}

// ================== warp-MMA bf16x3 GEMM, templated on TM ==================
// TM=128: 8 warps as 4m x 2n, warp tile 32x64.  TM=64: 2m x 4n, warp tile 32x32.
// 2 CTAs/SM via __launch_bounds__(256, 2).
#define PADK 40

template <int TM>
__global__ void __launch_bounds__(256, 2)
gemm_mma(const __nv_bfloat16* __restrict__ Ahi, const __nv_bfloat16* __restrict__ Alo,
         const __nv_bfloat16* __restrict__ Bhi, const __nv_bfloat16* __restrict__ Blo,
         const float* __restrict__ bias, float* __restrict__ outF,
         __nv_bfloat16* __restrict__ outHi, __nv_bfloat16* __restrict__ outLo,
         int npos, float scale, int mode)
{
    constexpr int ATILE = TM * PADK * 2;          // bytes per A tile
    constexpr int BTILE = 128 * PADK * 2;         // bytes per B tile
    constexpr int STAGE = 2 * ATILE + 2 * BTILE;  // Ahi,Alo,Bhi,Blo
    constexpr int MW = TM / 32;                   // warps along m
    constexpr int WN = 128 / (8 / MW);            // warp n extent (64 or 32)
    constexpr int NT = WN / 8;                    // 8 or 4
    constexpr int ACH = TM * 4;                   // 16B chunks per A tile
    constexpr int NCHUNK = 2 * ACH + 2 * 512;

    extern __shared__ char smem[];
    const uint32_t sb = smem_to_u32(smem);
    const int tid = threadIdx.x;
    const int wid = tid >> 5, lane = tid & 31;
    const int m0 = blockIdx.y * TM, n0 = blockIdx.x << 7;
    const int wm = (wid % MW) << 5;
    const int wn = (wid / MW) * WN;

    float acc[2][NT][4];
#pragma unroll
    for (int i = 0; i < 2; i++)
#pragma unroll
        for (int j = 0; j < NT; j++)
#pragma unroll
            for (int q = 0; q < 4; q++) acc[i][j][q] = 0.f;

    auto load_stage = [&](int s, int kb) {
#pragma unroll
        for (int i = 0; i < NCHUNK / 256; i++) {
            int cid = (i << 8) + tid;
            const __nv_bfloat16* gp; int rowbase; uint32_t toff; int local;
            if (cid < ACH)              { gp = Ahi; rowbase = m0; toff = 0;              local = cid; }
            else if (cid < 2 * ACH)     { gp = Alo; rowbase = m0; toff = ATILE;          local = cid - ACH; }
            else if (cid < 2 * ACH + 512){ gp = Bhi; rowbase = n0; toff = 2 * ATILE;      local = cid - 2 * ACH; }
            else                        { gp = Blo; rowbase = n0; toff = 2 * ATILE + BTILE; local = cid - 2 * ACH - 512; }
            int r = local >> 2, c = local & 3;
            const __nv_bfloat16* g = gp + (((size_t)(rowbase + r)) << 10) + kb + (c << 3);
            uint32_t sa = sb + (uint32_t)s * STAGE + toff + (uint32_t)(r * PADK + c * 8) * 2u;
            CP_ASYNC16(sa, g);
        }
        CP_COMMIT();
    };

    load_stage(0, 0);

    for (int it = 0; it < 32; it++) {
        const int s = it & 1;
        if (it + 1 < 32) { load_stage(s ^ 1, (it + 1) << 5); CP_WAIT(1); }
        else             { CP_WAIT(0); }
        __syncthreads();

        const uint32_t st = sb + (uint32_t)s * STAGE;
#pragma unroll
        for (int kk = 0; kk < 2; kk++) {
            const uint32_t coff = (uint32_t)(kk * 16 + ((lane >> 4) << 3)) * 2u;
            uint32_t ahi[2][4], alo[2][4];
#pragma unroll
            for (int mt = 0; mt < 2; mt++) {
                uint32_t ra = (uint32_t)((wm + mt * 16 + (lane & 15)) * PADK) * 2u + coff;
                ldm_x4(ahi[mt], st + ra);
                ldm_x4(alo[mt], st + ATILE + ra);
            }
#pragma unroll
            for (int ng = 0; ng < NT / 2; ng++) {
                uint32_t bhi[4], blo[4];
                uint32_t rb = (uint32_t)((wn + ng * 16 + (lane & 15)) * PADK) * 2u + coff;
                ldm_x4(bhi, st + 2 * ATILE + rb);
                ldm_x4(blo, st + 2 * ATILE + BTILE + rb);
#pragma unroll
                for (int mt = 0; mt < 2; mt++)
#pragma unroll
                    for (int sel = 0; sel < 2; sel++) {
                        const int nt = ng * 2 + sel;
                        mma16816(acc[mt][nt], ahi[mt], bhi[sel], bhi[sel + 2]);
                        mma16816(acc[mt][nt], ahi[mt], blo[sel], blo[sel + 2]);
                        mma16816(acc[mt][nt], alo[mt], bhi[sel], bhi[sel + 2]);
                    }
            }
        }
        __syncthreads();
    }

    // ---- epilogue ----
    const int qr = lane >> 2, qc = (lane & 3) << 1;
#pragma unroll
    for (int mt = 0; mt < 2; mt++) {
#pragma unroll
        for (int nt = 0; nt < NT; nt++) {
#pragma unroll
            for (int half = 0; half < 2; half++) {
                int row = m0 + wm + mt * 16 + qr + (half << 3);
                int col = n0 + wn + nt * 8 + qc;
                float v0 = (acc[mt][nt][half * 2 + 0] + bias[col])     * scale;
                float v1 = (acc[mt][nt][half * 2 + 1] + bias[col + 1]) * scale;
                if (mode == 2) {
                    *(float2*)&outF[(size_t)row * EDIM + col] = make_float2(v0, v1);
                } else {
                    int pos = row >> 2;              // B = 4
                    int b = row & 3;
                    int h = col >> 6, d = col & 63;
                    size_t o = ((size_t)(b * HDIM + h) * npos + pos) * DHD + d;
                    if (mode == 1) {
                        v0 = fast_sigmoid(v0); v1 = fast_sigmoid(v1);
                        *(float2*)&outF[o] = make_float2(v0, v1);
                    } else {
                        __nv_bfloat16 h0 = __float2bfloat16(v0), h1 = __float2bfloat16(v1);
                        __nv_bfloat16 l0 = __float2bfloat16(v0 - __bfloat162float(h0));
                        __nv_bfloat16 l1 = __float2bfloat16(v1 - __bfloat162float(h1));
                        *(__nv_bfloat162*)&outHi[o] = __nv_bfloat162(h0, h1);
                        *(__nv_bfloat162*)&outLo[o] = __nv_bfloat162(l0, l1);
                    }
                }
            }
        }
    }
}

#define GM_SMEM_128 (2 * (2 * 128 * PADK * 2 + 2 * 128 * PADK * 2))
#define GM_SMEM_64  (2 * (2 * 64  * PADK * 2 + 2 * 128 * PADK * 2))

// ---------------- per-row stats ----------------
__global__ void k_qstats(const __nv_bfloat16* __restrict__ qhi,
                         const __nv_bfloat16* __restrict__ qlo, float* __restrict__ ll)
{
    int gw = (blockIdx.x * blockDim.x + threadIdx.x) >> 5;
    int lane = threadIdx.x & 31;
    if (gw >= BH*LQ) return;
    const __nv_bfloat162* h = (const __nv_bfloat162*)(qhi + (size_t)gw * DHD);
    const __nv_bfloat162* l = (const __nv_bfloat162*)(qlo + (size_t)gw * DHD);
    __nv_bfloat162 hv = h[lane], lv = l[lane];
    float x0 = __bfloat162float(hv.x) + __bfloat162float(lv.x);
    float x1 = __bfloat162float(hv.y) + __bfloat162float(lv.y);
    float s = x0*x0 + x1*x1;
#pragma unroll
    for (int o = 16; o; o >>= 1) s += __shfl_xor_sync(0xffffffffu, s, o);
    if (!lane) ll[gw] = s;
}

__global__ void k_kstats(const __nv_bfloat16* __restrict__ k1hi, const __nv_bfloat16* __restrict__ k1lo,
                         const __nv_bfloat16* __restrict__ k2hi, const __nv_bfloat16* __restrict__ k2lo,
                         float* __restrict__ vv, float* __restrict__ aa, float* __restrict__ va)
{
    int gw = (blockIdx.x * blockDim.x + threadIdx.x) >> 5;
    int lane = threadIdx.x & 31;
    if (gw >= BH*SK) return;
    const __nv_bfloat162* ah = (const __nv_bfloat162*)(k1hi + (size_t)gw * DHD);
    const __nv_bfloat162* al = (const __nv_bfloat162*)(k1lo + (size_t)gw * DHD);
    const __nv_bfloat162* bh = (const __nv_bfloat162*)(k2hi + (size_t)gw * DHD);
    const __nv_bfloat162* bl = (const __nv_bfloat162*)(k2lo + (size_t)gw * DHD);
    __nv_bfloat162 a2 = ah[lane], a2l = al[lane], b2 = bh[lane], b2l = bl[lane];
    float a0 = __bfloat162float(a2.x) + __bfloat162float(a2l.x);
    float a1 = __bfloat162float(a2.y) + __bfloat162float(a2l.y);
    float b0 = __bfloat162float(b2.x) + __bfloat162float(b2l.x);
    float b1 = __bfloat162float(b2.y) + __bfloat162float(b2l.y);
    float svv = a0*a0 + a1*a1, saa = b0*b0 + b1*b1, sva = a0*b0 + a1*b1;
#pragma unroll
    for (int o = 16; o; o >>= 1) {
        svv += __shfl_xor_sync(0xffffffffu, svv, o);
        saa += __shfl_xor_sync(0xffffffffu, saa, o);
        sva += __shfl_xor_sync(0xffffffffu, sva, o);
    }
    if (!lane) { vv[gw] = svv; aa[gw] = saa; va[gw] = sva; }
}

// ================== logits via bf16x3 MMA + poly sqrt ==================
#define LG_PAD 72
#define LG_QT (64 * LG_PAD * 2)
#define LG_KT (128 * LG_PAD * 2)
#define LG_SMEM (2*LG_QT + 4*LG_KT)

__global__ void __launch_bounds__(256, 1)
k_logits_mma(const __nv_bfloat16* __restrict__ qhi, const __nv_bfloat16* __restrict__ qlo,
             const __nv_bfloat16* __restrict__ k1hi, const __nv_bfloat16* __restrict__ k1lo,
             const __nv_bfloat16* __restrict__ k2hi, const __nv_bfloat16* __restrict__ k2lo,
             const float* __restrict__ ll, const float* __restrict__ vv,
             const float* __restrict__ aa, const float* __restrict__ va,
             float* __restrict__ A)
{
    extern __shared__ char smem[];
    const uint32_t sb = smem_to_u32(smem);
    const int tid = threadIdx.x, wid = tid >> 5, lane = tid & 31;
    const int bh = blockIdx.z, l0 = blockIdx.y << 6, s0 = blockIdx.x << 7;
    const uint32_t oQh = 0, oQl = LG_QT, oK1h = 2*LG_QT, oK1l = 2*LG_QT + LG_KT,
                   oK2h = 2*LG_QT + 2*LG_KT, oK2l = 2*LG_QT + 3*LG_KT;

    {
        const __nv_bfloat16* qh = qhi + ((size_t)(bh * LQ + l0) << 6);
        const __nv_bfloat16* ql = qlo + ((size_t)(bh * LQ + l0) << 6);
#pragma unroll
        for (int i = tid; i < 512; i += 256) {
            int r = i >> 3, c = i & 7;
            uint32_t d = (uint32_t)(r * (LG_PAD*2) + c * 16);
            *(uint4*)(smem + oQh + d) = *(const uint4*)(qh + (r << 6) + (c << 3));
            *(uint4*)(smem + oQl + d) = *(const uint4*)(ql + (r << 6) + (c << 3));
        }
        const __nv_bfloat16* p1h = k1hi + ((size_t)(bh * SK + s0) << 6);
        const __nv_bfloat16* p1l = k1lo + ((size_t)(bh * SK + s0) << 6);
        const __nv_bfloat16* p2h = k2hi + ((size_t)(bh * SK + s0) << 6);
        const __nv_bfloat16* p2l = k2lo + ((size_t)(bh * SK + s0) << 6);
#pragma unroll
        for (int i = tid; i < 1024; i += 256) {
            int r = i >> 3, c = i & 7;
            uint32_t d = (uint32_t)(r * (LG_PAD*2) + c * 16);
            *(uint4*)(smem + oK1h + d) = *(const uint4*)(p1h + (r << 6) + (c << 3));
            *(uint4*)(smem + oK1l + d) = *(const uint4*)(p1l + (r << 6) + (c << 3));
            *(uint4*)(smem + oK2h + d) = *(const uint4*)(p2h + (r << 6) + (c << 3));
            *(uint4*)(smem + oK2l + d) = *(const uint4*)(p2l + (r << 6) + (c << 3));
        }
    }
    __syncthreads();

    const int wm = (wid & 1) << 5, wn = (wid >> 1) << 5;
    float lv[2][4][4] = {}, la[2][4][4] = {};
#pragma unroll
    for (int kk = 0; kk < 4; kk++) {
        const uint32_t coff = (uint32_t)(kk * 16 + ((lane >> 4) << 3)) * 2u;
        uint32_t af[2][4], alf[2][4];
#pragma unroll
        for (int mt = 0; mt < 2; mt++) {
            uint32_t ra = (uint32_t)((wm + mt * 16 + (lane & 15)) * LG_PAD) * 2u + coff;
            ldm_x4(af[mt],  sb + oQh + ra);
            ldm_x4(alf[mt], sb + oQl + ra);
        }
        uint32_t b1h[2][4], b1l[2][4], b2h[2][4], b2l[2][4];
#pragma unroll
        for (int ng = 0; ng < 2; ng++) {
            uint32_t rb = (uint32_t)((wn + ng * 16 + (lane & 15)) * LG_PAD) * 2u + coff;
            ldm_x4(b1h[ng], sb + oK1h + rb);
            ldm_x4(b1l[ng], sb + oK1l + rb);
            ldm_x4(b2h[ng], sb + oK2h + rb);
            ldm_x4(b2l[ng], sb + oK2l + rb);
        }
#pragma unroll
        for (int mt = 0; mt < 2; mt++)
#pragma unroll
            for (int nt = 0; nt < 4; nt++) {
                const int ng = nt >> 1, sel = nt & 1;
                mma16816(lv[mt][nt], af[mt],  b1h[ng][sel], b1h[ng][sel + 2]);
                mma16816(lv[mt][nt], af[mt],  b1l[ng][sel], b1l[ng][sel + 2]);
                mma16816(lv[mt][nt], alf[mt], b1h[ng][sel], b1h[ng][sel + 2]);
                mma16816(la[mt][nt], af[mt],  b2h[ng][sel], b2h[ng][sel + 2]);
                mma16816(la[mt][nt], af[mt],  b2l[ng][sel], b2l[ng][sel + 2]);
                mma16816(la[mt][nt], alf[mt], b2h[ng][sel], b2h[ng][sel + 2]);
            }
    }

    const int qr = lane >> 2, qc = (lane & 3) << 1;
    float vvc[8], aac[8], vac[8];
#pragma unroll
    for (int nt = 0; nt < 4; nt++)
#pragma unroll
        for (int j = 0; j < 2; j++) {
            int c = bh * SK + s0 + wn + nt * 8 + qc + j;
            vvc[nt*2+j] = __ldg(&vv[c]); aac[nt*2+j] = __ldg(&aa[c]); vac[nt*2+j] = __ldg(&va[c]);
        }
#pragma unroll
    for (int mt = 0; mt < 2; mt++)
#pragma unroll
        for (int half = 0; half < 2; half++) {
            int l = l0 + wm + mt * 16 + qr + (half << 3);
            float llr = __ldg(&ll[bh * LQ + l]);
            float* rowp = A + (((size_t)(bh * LQ + l)) << 10);
#pragma unroll
            for (int nt = 0; nt < 4; nt++) {
                float r2[2];
#pragma unroll
                for (int j = 0; j < 2; j++) {
                    float LV = lv[mt][nt][half * 2 + j];
                    float LA = la[mt][nt][half * 2 + j];
                    int ci = nt * 2 + j;
                    float det = llr * (vvc[ci] * aac[ci] - vac[ci] * vac[ci])
                              - LV * (LV * aac[ci] - LA * vac[ci])
                              + LA * (LV * vac[ci] - LA * vvc[ci]);
                    det = fmaxf(det, 1e-8f);
                    r2[j] = LV + LA - 1.5f * fast_sqrt(det);
                }
                *(float2*)&rowp[s0 + wn + nt * 8 + qc] = make_float2(r2[0], r2[1]);
            }
        }
}

// ---------------- softmax ----------------
__global__ void k_softmax(const float* __restrict__ A, __nv_bfloat16* __restrict__ Phi,
                          __nv_bfloat16* __restrict__ Plo)
{
    const int row = blockIdx.x;
    const float* p = A + (size_t)row * SK;
    const int t = threadIdx.x;
    float4 x = *(const float4*)(p + t * 4);
    float m = fmaxf(fmaxf(x.x, x.y), fmaxf(x.z, x.w));
    __shared__ float sred[8];
    __shared__ float sinv;
#pragma unroll
    for (int o = 16; o; o >>= 1) m = fmaxf(m, __shfl_xor_sync(0xffffffffu, m, o));
    if ((t & 31) == 0) sred[t >> 5] = m;
    __syncthreads();
    if (t < 8) {
        float v = sred[t];
#pragma unroll
        for (int o = 4; o; o >>= 1) v = fmaxf(v, __shfl_xor_sync(0xffu, v, o));
        sred[t] = v;
    }
    __syncthreads();
    m = sred[0];
    float e0 = fast_exp(x.x - m), e1 = fast_exp(x.y - m);
    float e2 = fast_exp(x.z - m), e3 = fast_exp(x.w - m);
    float s = (e0 + e1) + (e2 + e3);
#pragma unroll
    for (int o = 16; o; o >>= 1) s += __shfl_xor_sync(0xffffffffu, s, o);
    __shared__ float sred2[8];
    if ((t & 31) == 0) sred2[t >> 5] = s;
    __syncthreads();
    if (t < 8) {
        float v = sred2[t];
#pragma unroll
        for (int o = 4; o; o >>= 1) v += __shfl_xor_sync(0xffu, v, o);
        if (t == 0) sinv = 1.0f / v;
    }
    __syncthreads();
    float inv = sinv;
    float v0 = e0 * inv, v1 = e1 * inv, v2 = e2 * inv, v3 = e3 * inv;
    __nv_bfloat16 h0 = __float2bfloat16(v0), h1 = __float2bfloat16(v1);
    __nv_bfloat16 h2 = __float2bfloat16(v2), h3 = __float2bfloat16(v3);
    __nv_bfloat16 l0 = __float2bfloat16(v0 - __bfloat162float(h0));
    __nv_bfloat16 l1 = __float2bfloat16(v1 - __bfloat162float(h1));
    __nv_bfloat16 l2 = __float2bfloat16(v2 - __bfloat162float(h2));
    __nv_bfloat16 l3 = __float2bfloat16(v3 - __bfloat162float(h3));
    size_t o = (size_t)row * SK + t * 4;
    ((__nv_bfloat162*)(Phi + o))[0] = __nv_bfloat162(h0, h1);
    ((__nv_bfloat162*)(Phi + o))[1] = __nv_bfloat162(h2, h3);
    ((__nv_bfloat162*)(Plo + o))[0] = __nv_bfloat162(l0, l1);
    ((__nv_bfloat162*)(Plo + o))[1] = __nv_bfloat162(l2, l3);
}

// ---------------- head-average ----------------
__global__ void k_avg(const __nv_bfloat16* __restrict__ Phi, const __nv_bfloat16* __restrict__ Plo,
                      float* __restrict__ avg)
{
    size_t idx = (size_t)blockIdx.x * 256 + threadIdx.x;
    if (idx >= (size_t)BDIM * LQ * SK) return;
    int s = idx & (SK - 1);
    int l = (idx >> 10) & (LQ - 1);
    int b = (int)(idx >> 19);
    size_t base = ((size_t)b * HDIM) * LQ * SK + (size_t)l * SK + s;
    float acc = 0.f;
#pragma unroll
    for (int h = 0; h < HDIM; h++) {
        size_t o = base + (size_t)h * LQ * SK;
        acc += __bfloat162float(Phi[o]) + __bfloat162float(Plo[o]);
    }
    avg[idx] = acc * (1.f / HDIM);
}

// ================== attn @ V + gate + split -> cb ==================
#define AV_PAD 72
#define AV_T (64 * AV_PAD * 2)
#define AV_STAGE (6 * AV_T)
#define AV_SMEM (2 * AV_STAGE)

__global__ void __launch_bounds__(256, 1)
k_av_mma(const __nv_bfloat16* __restrict__ athi, const __nv_bfloat16* __restrict__ atlo,
         const __nv_bfloat16* __restrict__ v1hi, const __nv_bfloat16* __restrict__ v1lo,
         const __nv_bfloat16* __restrict__ v2hi, const __nv_bfloat16* __restrict__ v2lo,
         const float* __restrict__ G1, const float* __restrict__ G2,
         __nv_bfloat16* __restrict__ cbhi, __nv_bfloat16* __restrict__ cblo)
{
    extern __shared__ char smem[];
    const uint32_t sb = smem_to_u32(smem);
    const int tid = threadIdx.x, wid = tid >> 5, lane = tid & 31;
    const int bh = blockIdx.y, l0 = blockIdx.x << 6;
    const int wm = (wid & 1) << 5, wn = (wid >> 1) << 4;

    float acc1[2][2][4] = {}, acc2[2][2][4] = {};

#define AV_LOAD(stg, s0k) do { \
    _Pragma("unroll") \
    for (int i = 0; i < 12; i++) { \
        int id = (i << 8) + tid; \
        int a = id >> 9; \
        int rr = (id >> 3) & 63; \
        int c = id & 7; \
        const __nv_bfloat16* g; \
        if (a < 2) g = (a ? atlo : athi) + (((size_t)(bh * LQ + l0 + rr)) << 10) + (s0k) + (c << 3); \
        else { \
            const __nv_bfloat16* vb = (a == 2) ? v1hi : (a == 3) ? v1lo : (a == 4) ? v2hi : v2lo; \
            g = vb + (((size_t)(bh * SK + (s0k) + rr)) << 6) + (c << 3); \
        } \
        uint32_t sa = sb + (uint32_t)(stg) * AV_STAGE + (uint32_t)a * AV_T + (uint32_t)(rr * (AV_PAD*2) + c * 16); \
        CP_ASYNC16(sa, g); \
    } \
    CP_COMMIT(); \
} while (0)

    AV_LOAD(0, 0);

    for (int ch = 0; ch < 16; ch++) {
        const int stg = ch & 1;
        if (ch + 1 < 16) { AV_LOAD(stg ^ 1, (ch + 1) << 6); CP_WAIT(1); }
        else             { CP_WAIT(0); }
        __syncthreads();

        const uint32_t st = sb + (uint32_t)stg * AV_STAGE;
#pragma unroll
        for (int kk = 0; kk < 4; kk++) {
            const uint32_t coff = (uint32_t)(kk * 16 + ((lane >> 4) << 3)) * 2u;
            uint32_t af[2][4], alf[2][4];
#pragma unroll
            for (int mt = 0; mt < 2; mt++) {
                uint32_t ra = (uint32_t)((wm + mt * 16 + (lane & 15)) * AV_PAD) * 2u + coff;
                ldm_x4(af[mt],  st + ra);
                ldm_x4(alf[mt], st + AV_T + ra);
            }
            uint32_t bv1h[4], bv1l[4], bv2h[4], bv2l[4];
            {
                uint32_t rb = (uint32_t)((kk * 16 + (lane & 15)) * AV_PAD + wn + ((lane >> 4) << 3)) * 2u;
                ldm_x4_t(bv1h, st + 2 * AV_T + rb);
                ldm_x4_t(bv1l, st + 3 * AV_T + rb);
                ldm_x4_t(bv2h, st + 4 * AV_T + rb);
                ldm_x4_t(bv2l, st + 5 * AV_T + rb);
            }
#pragma unroll
            for (int mt = 0; mt < 2; mt++)
#pragma unroll
                for (int nt = 0; nt < 2; nt++) {
                    mma16816(acc1[mt][nt], af[mt],  bv1h[nt*2], bv1h[nt*2+1]);
                    mma16816(acc1[mt][nt], af[mt],  bv1l[nt*2], bv1l[nt*2+1]);
                    mma16816(acc1[mt][nt], alf[mt], bv1h[nt*2], bv1h[nt*2+1]);
                    mma16816(acc2[mt][nt], af[mt],  bv2h[nt*2], bv2h[nt*2+1]);
                    mma16816(acc2[mt][nt], af[mt],  bv2l[nt*2], bv2l[nt*2+1]);
                    mma16816(acc2[mt][nt], alf[mt], bv2h[nt*2], bv2h[nt*2+1]);
                }
        }
        __syncthreads();
    }

    const int qr = lane >> 2, qc = (lane & 3) << 1;
    const int b_ = bh >> 4, h_ = bh & 15;
#pragma unroll
    for (int mt = 0; mt < 2; mt++)
#pragma unroll
        for (int half = 0; half < 2; half++) {
            int l = l0 + wm + mt * 16 + qr + (half << 3);
            const float* g1r = G1 + ((size_t)(bh * LQ + l)) * DHD;
            const float* g2r = G2 + ((size_t)(bh * LQ + l)) * DHD;
            size_t rowo = ((size_t)(l * BDIM + b_)) << 10;
#pragma unroll
            for (int nt = 0; nt < 2; nt++) {
                int d = wn + nt * 8 + qc;
                float2 g1 = *(const float2*)&g1r[d];
                float2 g2 = *(const float2*)&g2r[d];
                float c0 = (acc1[mt][nt][half*2+0] * g1.x + acc2[mt][nt][half*2+0] * g2.x) * 0.5f;
                float c1 = (acc1[mt][nt][half*2+1] * g1.y + acc2[mt][nt][half*2+1] * g2.y) * 0.5f;
                __nv_bfloat16 h0 = __float2bfloat16(c0), h1 = __float2bfloat16(c1);
                __nv_bfloat16 l0b = __float2bfloat16(c0 - __bfloat162float(h0));
                __nv_bfloat16 l1b = __float2bfloat16(c1 - __bfloat162float(h1));
                size_t o = rowo + h_ * DHD + d;
                *(__nv_bfloat162*)&cbhi[o] = __nv_bfloat162(h0, h1);
                *(__nv_bfloat162*)&cblo[o] = __nv_bfloat162(l0b, l1b);
            }
        }
#undef AV_LOAD
}

// ---------------- launch ----------------
extern "C" void kernel_launch(void* const* d_in, const int* in_sizes, int n_in,
                              void* d_out, int out_size)
{
    const float* query = (const float*)d_in[0];
    const float* mod1  = (const float*)d_in[1];
    const float* mod2  = (const float*)d_in[2];
    WPtrs wp;
    const float* bi[8];
    for (int i = 0; i < 8; i++) {
        wp.p[i] = (const float*)d_in[3 + 2*i];
        bi[i]   = (const float*)d_in[4 + 2*i];
    }
    float* out = (float*)d_out;
    float* avg_out = out + (size_t)LQ * BDIM * EDIM;

    float *G1h, *G2h, *ll, *vv, *aa, *va, *Attn;
    cudaGetSymbolAddress((void**)&G1h, g_G1h);
    cudaGetSymbolAddress((void**)&G2h, g_G2h);
    cudaGetSymbolAddress((void**)&ll,  g_ll);
    cudaGetSymbolAddress((void**)&vv,  g_vv);
    cudaGetSymbolAddress((void**)&aa,  g_aa);
    cudaGetSymbolAddress((void**)&va,  g_va);
    cudaGetSymbolAddress((void**)&Attn, g_Attn);

    __nv_bfloat16 *qhi,*qlo,*k1hi,*k1lo,*k2hi,*k2lo,*v1hi,*v1lo,*v2hi,*v2lo,*athi,*atlo;
    __nv_bfloat16 *xq_hi,*xq_lo,*m1_hi,*m1_lo,*m2_hi,*m2_lo,*cb_hi,*cb_lo,*wt_hi,*wt_lo;
    cudaGetSymbolAddress((void**)&qhi,  g_q_hi);  cudaGetSymbolAddress((void**)&qlo,  g_q_lo);
    cudaGetSymbolAddress((void**)&k1hi, g_k1_hi); cudaGetSymbolAddress((void**)&k1lo, g_k1_lo);
    cudaGetSymbolAddress((void**)&k2hi, g_k2_hi); cudaGetSymbolAddress((void**)&k2lo, g_k2_lo);
    cudaGetSymbolAddress((void**)&v1hi, g_v1_hi); cudaGetSymbolAddress((void**)&v1lo, g_v1_lo);
    cudaGetSymbolAddress((void**)&v2hi, g_v2_hi); cudaGetSymbolAddress((void**)&v2lo, g_v2_lo);
    cudaGetSymbolAddress((void**)&athi, g_at_hi); cudaGetSymbolAddress((void**)&atlo, g_at_lo);
    cudaGetSymbolAddress((void**)&xq_hi, g_xq_hi); cudaGetSymbolAddress((void**)&xq_lo, g_xq_lo);
    cudaGetSymbolAddress((void**)&m1_hi, g_m1_hi); cudaGetSymbolAddress((void**)&m1_lo, g_m1_lo);
    cudaGetSymbolAddress((void**)&m2_hi, g_m2_hi); cudaGetSymbolAddress((void**)&m2_lo, g_m2_lo);
    cudaGetSymbolAddress((void**)&cb_hi, g_cb_hi); cudaGetSymbolAddress((void**)&cb_lo, g_cb_lo);
    cudaGetSymbolAddress((void**)&wt_hi, g_wt_hi); cudaGetSymbolAddress((void**)&wt_lo, g_wt_lo);

    cudaFuncSetAttribute(gemm_mma<128>, cudaFuncAttributeMaxDynamicSharedMemorySize, GM_SMEM_128);
    cudaFuncSetAttribute(gemm_mma<64>,  cudaFuncAttributeMaxDynamicSharedMemorySize, GM_SMEM_64);
    cudaFuncSetAttribute(k_logits_mma,  cudaFuncAttributeMaxDynamicSharedMemorySize, LG_SMEM);
    cudaFuncSetAttribute(k_av_mma,      cudaFuncAttributeMaxDynamicSharedMemorySize, AV_SMEM);

    k_split_all<<<10240, 256>>>(query, mod1, mod2, xq_hi, xq_lo, m1_hi, m1_lo, m2_hi, m2_lo);
    k_wsplit_all<<<dim3(32, 32, 8), dim3(32, 8)>>>(wp, wt_hi, wt_lo);

    dim3 gq(8, 32);   // TM=64: 2048 rows / 64
    dim3 gk(8, 32);   // TM=128: 4096 rows / 128
    size_t WSZ = (size_t)1024*1024;
    gemm_mma<64> <<<gq, 256, GM_SMEM_64 >>>(xq_hi, xq_lo, wt_hi+0*WSZ, wt_lo+0*WSZ, bi[0], nullptr, qhi,  qlo,  LQ, 0.125f, 0);
    gemm_mma<128><<<gk, 256, GM_SMEM_128>>>(m1_hi, m1_lo, wt_hi+1*WSZ, wt_lo+1*WSZ, bi[1], nullptr, k1hi, k1lo, SK, 1.f,    0);
    gemm_mma<128><<<gk, 256, GM_SMEM_128>>>(m2_hi, m2_lo, wt_hi+2*WSZ, wt_lo+2*WSZ, bi[2], nullptr, k2hi, k2lo, SK, 1.f,    0);
    gemm_mma<128><<<gk, 256, GM_SMEM_128>>>(m1_hi, m1_lo, wt_hi+3*WSZ, wt_lo+3*WSZ, bi[3], nullptr, v1hi, v1lo, SK, 1.f,    0);
    gemm_mma<128><<<gk, 256, GM_SMEM_128>>>(m2_hi, m2_lo, wt_hi+4*WSZ, wt_lo+4*WSZ, bi[4], nullptr, v2hi, v2lo, SK, 1.f,    0);
    gemm_mma<64> <<<gq, 256, GM_SMEM_64 >>>(xq_hi, xq_lo, wt_hi+5*WSZ, wt_lo+5*WSZ, bi[5], G1h, nullptr, nullptr, LQ, 1.f, 1);
    gemm_mma<64> <<<gq, 256, GM_SMEM_64 >>>(xq_hi, xq_lo, wt_hi+6*WSZ, wt_lo+6*WSZ, bi[6], G2h, nullptr, nullptr, LQ, 1.f, 1);

    k_qstats<<<(BH*LQ*32 + 255)/256, 256>>>(qhi, qlo, ll);
    k_kstats<<<(BH*SK*32 + 255)/256, 256>>>(k1hi, k1lo, k2hi, k2lo, vv, aa, va);

    k_logits_mma<<<dim3(SK/128, LQ/64, BH), 256, LG_SMEM>>>(
        qhi, qlo, k1hi, k1lo, k2hi, k2lo, ll, vv, aa, va, Attn);
    k_softmax<<<BH*LQ, 256>>>(Attn, athi, atlo);
    if ((size_t)out_size >= 2ULL * LQ * BDIM * EDIM)
        k_avg<<<(BDIM*LQ*SK + 255)/256, 256>>>(athi, atlo, avg_out);
    k_av_mma<<<dim3(LQ/64, BH), 256, AV_SMEM>>>(athi, atlo, v1hi, v1lo, v2hi, v2lo,
                                                G1h, G2h, cb_hi, cb_lo);
    gemm_mma<64> <<<gq, 256, GM_SMEM_64 >>>(cb_hi, cb_lo, wt_hi+7*WSZ, wt_lo+7*WSZ, bi[7], out,
                                            nullptr, nullptr, LQ, 1.f, 2);
}